// round 2
// baseline (speedup 1.0000x reference)
#include <cuda_runtime.h>
#include <math.h>
#include <stdint.h>

#define B_  2
#define S_  2048
#define D_  2048
#define H_  16
#define DH_ 128
#define M_  (B_*S_)          // 4096 rows (b*S+s)
#define SCALE_ 0.08838834764831845f  // 1/sqrt(128)

// ---------------- scratch (device globals; no allocations) ----------------
__device__ float g_q   [(size_t)M_*H_*DH_];   // [b,s,h,d]  33.5 MB
__device__ float g_kv  [(size_t)M_*2*DH_];    // [b,s, 2*128]
__device__ float g_k   [(size_t)M_*DH_];      // [b,s,d]
__device__ float g_v   [(size_t)M_*DH_];
__device__ float g_attn[(size_t)M_*H_*DH_];   // [b,s,h,d]
__device__ float g_cos [S_*(DH_/2)];
__device__ float g_sin [S_*(DH_/2)];

// ---------------- RoPE table (fp32, matches jnp op ordering) ----------------
__global__ void rope_table_kernel() {
    int idx = blockIdx.x * blockDim.x + threadIdx.x;
    if (idx >= S_*(DH_/2)) return;
    int s = idx >> 6;
    int i = idx & 63;
    float expo = (float)(2*i) / 128.0f;
    float inv  = 1.0f / powf(10000.0f, expo);
    float ang  = (float)s * inv;
    g_cos[idx] = cosf(ang);
    g_sin[idx] = sinf(ang);
}

// ---------------- tiled fp32 GEMM: C[M,N] = A[M,K] @ W[N,K]^T + bias ----------------
#define BM 128
#define BN 128
#define BK 16
__global__ __launch_bounds__(256, 2)
void gemm_bias_kernel(const float* __restrict__ A, const float* __restrict__ W,
                      const float* __restrict__ bias, float* __restrict__ C,
                      int M, int N, int K) {
    __shared__ float As[BK][BM+4];
    __shared__ float Bs[BK][BN+4];
    const int tid = threadIdx.x;
    const int tx = tid & 15, ty = tid >> 4;
    const float* Ablk = A + (size_t)blockIdx.y * BM * K;
    const float* Wblk = W + (size_t)blockIdx.x * BN * K;

    float c[8][8];
    #pragma unroll
    for (int i = 0; i < 8; ++i)
        #pragma unroll
        for (int j = 0; j < 8; ++j) c[i][j] = 0.f;

    const int lr = tid >> 2;           // 0..63
    const int cg = (tid & 3) * 4;      // 0,4,8,12

    for (int k0 = 0; k0 < K; k0 += BK) {
        #pragma unroll
        for (int it = 0; it < 2; ++it) {
            int r = lr + it*64;
            float4 va = *(const float4*)(Ablk + (size_t)r*K + k0 + cg);
            As[cg+0][r] = va.x; As[cg+1][r] = va.y; As[cg+2][r] = va.z; As[cg+3][r] = va.w;
            float4 vb = *(const float4*)(Wblk + (size_t)r*K + k0 + cg);
            Bs[cg+0][r] = vb.x; Bs[cg+1][r] = vb.y; Bs[cg+2][r] = vb.z; Bs[cg+3][r] = vb.w;
        }
        __syncthreads();
        #pragma unroll
        for (int kk = 0; kk < BK; ++kk) {
            float a[8], b[8];
            *(float4*)&a[0] = *(const float4*)&As[kk][ty*8];
            *(float4*)&a[4] = *(const float4*)&As[kk][ty*8+4];
            *(float4*)&b[0] = *(const float4*)&Bs[kk][tx*8];
            *(float4*)&b[4] = *(const float4*)&Bs[kk][tx*8+4];
            #pragma unroll
            for (int i = 0; i < 8; ++i)
                #pragma unroll
                for (int j = 0; j < 8; ++j)
                    c[i][j] = fmaf(a[i], b[j], c[i][j]);
        }
        __syncthreads();
    }

    const int ncol = blockIdx.x*BN + tx*8;
    float4 bb0 = *(const float4*)(bias + ncol);
    float4 bb1 = *(const float4*)(bias + ncol + 4);
    #pragma unroll
    for (int i = 0; i < 8; ++i) {
        float* Crow = C + (size_t)(blockIdx.y*BM + ty*8 + i) * N + ncol;
        float4 o0 = make_float4(c[i][0]+bb0.x, c[i][1]+bb0.y, c[i][2]+bb0.z, c[i][3]+bb0.w);
        float4 o1 = make_float4(c[i][4]+bb1.x, c[i][5]+bb1.y, c[i][6]+bb1.z, c[i][7]+bb1.w);
        *(float4*)(Crow)     = o0;
        *(float4*)(Crow + 4) = o1;
    }
}

// ---------------- RoPE on q (in place) ----------------
__global__ void rope_q_kernel() {
    int idx = blockIdx.x * blockDim.x + threadIdx.x;   // over (row*H + h)*64 + i
    if (idx >= M_*H_*64) return;
    int i    = idx & 63;
    int qrow = idx >> 6;                  // 0..65535 = (b*S+s)*H + h
    int s    = (qrow >> 4) & (S_-1);
    float* qp = g_q + (size_t)qrow * DH_;
    float x1 = qp[i], x2 = qp[i+64];
    float cv = g_cos[s*64 + i], sv = g_sin[s*64 + i];
    qp[i]    = x1*cv - x2*sv;
    qp[i+64] = x2*cv + x1*sv;
}

// ---------------- split kv -> k (RoPE), v ----------------
__global__ void kv_split_kernel() {
    int idx = blockIdx.x * blockDim.x + threadIdx.x;   // row*64 + i
    if (idx >= M_*64) return;
    int i   = idx & 63;
    int row = idx >> 6;
    int s   = row & (S_-1);
    const float* kvr = g_kv + (size_t)row * 256;
    float x1 = kvr[i], x2 = kvr[i+64];
    float cv = g_cos[s*64 + i], sv = g_sin[s*64 + i];
    g_k[(size_t)row*DH_ + i]      = x1*cv - x2*sv;
    g_k[(size_t)row*DH_ + i + 64] = x2*cv + x1*sv;
    g_v[(size_t)row*DH_ + i]      = kvr[128 + i];
    g_v[(size_t)row*DH_ + i + 64] = kvr[128 + i + 64];
}

// ---------------- flash attention (causal, MQA) ----------------
// tile: 64 q-rows x 64 k-cols, DH=128. 256 threads (16x16), 4x4 score tile,
// 4x8 acc tile per thread. K stored transposed in smem; V reuses same buffer.
#define QS_STRIDE 132
#define KT_STRIDE 68
#define PS_STRIDE 68
#define FA_SMEM_FLOATS (64*QS_STRIDE + 128*KT_STRIDE + 64*PS_STRIDE)
#define FA_SMEM_BYTES  (FA_SMEM_FLOATS * 4)

__global__ __launch_bounds__(256, 2)
void flash_attn_kernel() {
    extern __shared__ float sm[];
    float* Qs = sm;                      // [64][132]
    float* KT = Qs + 64*QS_STRIDE;       // K: [128][68] transposed / V: [64][132]
    float* Ps = KT + 128*KT_STRIDE;      // [64][68]

    const int tid = threadIdx.x;
    const int tx = tid & 15, ty = tid >> 4;
    const int qt = blockIdx.x;
    const int b  = blockIdx.y >> 4;
    const int h  = blockIdx.y & 15;

    // load + pre-scale Q tile
    const float* qbase = g_q + (((size_t)(b*S_ + qt*64))*H_ + h) * DH_;
    #pragma unroll
    for (int it = 0; it < 8; ++it) {
        int f4 = tid + it*256;           // 64*32 float4s
        int r = f4 >> 5, c4 = f4 & 31;
        float4 v = *(const float4*)(qbase + (size_t)r*(H_*DH_) + c4*4);
        v.x *= SCALE_; v.y *= SCALE_; v.z *= SCALE_; v.w *= SCALE_;
        *(float4*)&Qs[r*QS_STRIDE + c4*4] = v;
    }

    float m_i[4], l_i[4], acc[4][8];
    #pragma unroll
    for (int i = 0; i < 4; ++i) {
        m_i[i] = -1e30f; l_i[i] = 0.f;
        #pragma unroll
        for (int j = 0; j < 8; ++j) acc[i][j] = 0.f;
    }
    __syncthreads();

    for (int kt = 0; kt <= qt; ++kt) {
        // ---- load K tile transposed: KT[d][kr] ----
        const float* kbase = g_k + ((size_t)b*S_ + kt*64) * DH_;
        #pragma unroll
        for (int it = 0; it < 8; ++it) {
            int f4 = tid + it*256;       // 32(d4) * 64(kr)
            int d4 = f4 >> 6, kr = f4 & 63;
            float4 v = *(const float4*)(kbase + (size_t)kr*DH_ + d4*4);
            KT[(d4*4+0)*KT_STRIDE + kr] = v.x;
            KT[(d4*4+1)*KT_STRIDE + kr] = v.y;
            KT[(d4*4+2)*KT_STRIDE + kr] = v.z;
            KT[(d4*4+3)*KT_STRIDE + kr] = v.w;
        }
        __syncthreads();

        // ---- scores: s[i][j] = sum_d Qs[ty*4+i][d] * KT[d][tx*4+j] ----
        float s[4][4];
        #pragma unroll
        for (int i = 0; i < 4; ++i)
            #pragma unroll
            for (int j = 0; j < 4; ++j) s[i][j] = 0.f;

        #pragma unroll 4
        for (int d4 = 0; d4 < 32; ++d4) {
            float4 a[4], bb[4];
            #pragma unroll
            for (int i = 0; i < 4; ++i)
                a[i] = *(const float4*)&Qs[(ty*4+i)*QS_STRIDE + d4*4];
            #pragma unroll
            for (int u = 0; u < 4; ++u)
                bb[u] = *(const float4*)&KT[(d4*4+u)*KT_STRIDE + tx*4];
            #pragma unroll
            for (int i = 0; i < 4; ++i) {
                s[i][0] = fmaf(a[i].x, bb[0].x, s[i][0]);
                s[i][1] = fmaf(a[i].x, bb[0].y, s[i][1]);
                s[i][2] = fmaf(a[i].x, bb[0].z, s[i][2]);
                s[i][3] = fmaf(a[i].x, bb[0].w, s[i][3]);
                s[i][0] = fmaf(a[i].y, bb[1].x, s[i][0]);
                s[i][1] = fmaf(a[i].y, bb[1].y, s[i][1]);
                s[i][2] = fmaf(a[i].y, bb[1].z, s[i][2]);
                s[i][3] = fmaf(a[i].y, bb[1].w, s[i][3]);
                s[i][0] = fmaf(a[i].z, bb[2].x, s[i][0]);
                s[i][1] = fmaf(a[i].z, bb[2].y, s[i][1]);
                s[i][2] = fmaf(a[i].z, bb[2].z, s[i][2]);
                s[i][3] = fmaf(a[i].z, bb[2].w, s[i][3]);
                s[i][0] = fmaf(a[i].w, bb[3].x, s[i][0]);
                s[i][1] = fmaf(a[i].w, bb[3].y, s[i][1]);
                s[i][2] = fmaf(a[i].w, bb[3].z, s[i][2]);
                s[i][3] = fmaf(a[i].w, bb[3].w, s[i][3]);
            }
        }

        // causal mask (only the diagonal tile needs it)
        if (kt == qt) {
            #pragma unroll
            for (int i = 0; i < 4; ++i)
                #pragma unroll
                for (int j = 0; j < 4; ++j)
                    if (tx*4+j > ty*4+i) s[i][j] = -1e30f;
        }

        // online softmax update per row (reduce across tx group of 16 lanes)
        #pragma unroll
        for (int i = 0; i < 4; ++i) {
            float rm = fmaxf(fmaxf(s[i][0], s[i][1]), fmaxf(s[i][2], s[i][3]));
            rm = fmaxf(rm, __shfl_xor_sync(0xffffffffu, rm, 1, 16));
            rm = fmaxf(rm, __shfl_xor_sync(0xffffffffu, rm, 2, 16));
            rm = fmaxf(rm, __shfl_xor_sync(0xffffffffu, rm, 4, 16));
            rm = fmaxf(rm, __shfl_xor_sync(0xffffffffu, rm, 8, 16));
            float mn   = fmaxf(m_i[i], rm);
            float corr = __expf(m_i[i] - mn);
            float rs = 0.f;
            #pragma unroll
            for (int j = 0; j < 4; ++j) {
                float p = __expf(s[i][j] - mn);
                Ps[(ty*4+i)*PS_STRIDE + tx*4 + j] = p;
                rs += p;
            }
            rs += __shfl_xor_sync(0xffffffffu, rs, 1, 16);
            rs += __shfl_xor_sync(0xffffffffu, rs, 2, 16);
            rs += __shfl_xor_sync(0xffffffffu, rs, 4, 16);
            rs += __shfl_xor_sync(0xffffffffu, rs, 8, 16);
            l_i[i] = l_i[i]*corr + rs;
            m_i[i] = mn;
            #pragma unroll
            for (int j = 0; j < 8; ++j) acc[i][j] *= corr;
        }
        __syncthreads();   // KT reads + Ps writes done

        // ---- load V tile (row-major) into same buffer ----
        const float* vbase = g_v + ((size_t)b*S_ + kt*64) * DH_;
        #pragma unroll
        for (int it = 0; it < 8; ++it) {
            int f4 = tid + it*256;
            int r = f4 >> 5, c4 = f4 & 31;
            *(float4*)&KT[r*QS_STRIDE + c4*4] =
                *(const float4*)(vbase + (size_t)r*DH_ + c4*4);
        }
        __syncthreads();

        // ---- PV: acc[i][0..7] += Ps[row][kk] * V[kk][tx*8 ..] ----
        #pragma unroll 4
        for (int kk = 0; kk < 64; ++kk) {
            float4 v0 = *(const float4*)&KT[kk*QS_STRIDE + tx*8];
            float4 v1 = *(const float4*)&KT[kk*QS_STRIDE + tx*8 + 4];
            #pragma unroll
            for (int i = 0; i < 4; ++i) {
                float p = Ps[(ty*4+i)*PS_STRIDE + kk];
                acc[i][0] = fmaf(p, v0.x, acc[i][0]);
                acc[i][1] = fmaf(p, v0.y, acc[i][1]);
                acc[i][2] = fmaf(p, v0.z, acc[i][2]);
                acc[i][3] = fmaf(p, v0.w, acc[i][3]);
                acc[i][4] = fmaf(p, v1.x, acc[i][4]);
                acc[i][5] = fmaf(p, v1.y, acc[i][5]);
                acc[i][6] = fmaf(p, v1.z, acc[i][6]);
                acc[i][7] = fmaf(p, v1.w, acc[i][7]);
            }
        }
        __syncthreads();   // V/Ps consumed before next iteration overwrites
    }

    // epilogue: normalize and store to g_attn [b,s,h,d]
    #pragma unroll
    for (int i = 0; i < 4; ++i) {
        float inv = 1.0f / l_i[i];
        int row = qt*64 + ty*4 + i;
        float* outp = g_attn + (((size_t)(b*S_ + row))*H_ + h) * DH_ + tx*8;
        float4 o0 = make_float4(acc[i][0]*inv, acc[i][1]*inv, acc[i][2]*inv, acc[i][3]*inv);
        float4 o1 = make_float4(acc[i][4]*inv, acc[i][5]*inv, acc[i][6]*inv, acc[i][7]*inv);
        *(float4*)(outp)     = o0;
        *(float4*)(outp + 4) = o1;
    }
}

// ---------------- launch ----------------
extern "C" void kernel_launch(void* const* d_in, const int* in_sizes, int n_in,
                              void* d_out, int out_size) {
    const float* x        = (const float*)d_in[0];
    const float* q_weight = (const float*)d_in[1];
    const float* q_bias   = (const float*)d_in[2];
    const float* kv_weight= (const float*)d_in[3];
    const float* kv_bias  = (const float*)d_in[4];
    const float* o_weight = (const float*)d_in[5];
    const float* o_bias   = (const float*)d_in[6];
    float* out = (float*)d_out;

    float *pq, *pkv, *pattn;
    cudaGetSymbolAddress((void**)&pq,    g_q);
    cudaGetSymbolAddress((void**)&pkv,   g_kv);
    cudaGetSymbolAddress((void**)&pattn, g_attn);

    cudaFuncSetAttribute(flash_attn_kernel,
                         cudaFuncAttributeMaxDynamicSharedMemorySize, FA_SMEM_BYTES);

    // 1. RoPE tables
    rope_table_kernel<<<(S_*64 + 255)/256, 256>>>();
    // 2. Q projection
    gemm_bias_kernel<<<dim3(D_/BN, M_/BM), 256>>>(x, q_weight, q_bias, pq, M_, D_, D_);
    // 3. KV projection
    gemm_bias_kernel<<<dim3(256/BN, M_/BM), 256>>>(x, kv_weight, kv_bias, pkv, M_, 256, D_);
    // 4. RoPE on q
    rope_q_kernel<<<(M_*H_*64 + 255)/256, 256>>>();
    // 5. split kv, RoPE on k
    kv_split_kernel<<<(M_*64 + 255)/256, 256>>>();
    // 6. attention
    flash_attn_kernel<<<dim3(S_/64, B_*H_), 256, FA_SMEM_BYTES>>>();
    // 7. O projection -> d_out
    gemm_bias_kernel<<<dim3(D_/BN, M_/BM), 256>>>(pattn, o_weight, o_bias, out, M_, D_, D_);
}

// round 4
// speedup vs baseline: 1.4517x; 1.4517x over previous
#include <cuda_runtime.h>
#include <cuda_bf16.h>
#include <math.h>
#include <stdint.h>

#define B_  2
#define S_  2048
#define D_  2048
#define H_  16
#define DH_ 128
#define M_  (B_*S_)          // 4096 rows (b*S+s)
#define SCALE_ 0.08838834764831845f  // 1/sqrt(128)

// ---------------- scratch (device globals; no allocations) ----------------
__device__ float g_q   [(size_t)M_*H_*DH_];   // [b,s,h,d]  33.5 MB
__device__ float g_kv  [(size_t)M_*2*DH_];    // [b,s, 2*128]
__device__ float g_k   [(size_t)M_*DH_];      // [b,s,d]
__device__ float g_v   [(size_t)M_*DH_];
__device__ float g_attn[(size_t)M_*H_*DH_];   // [b,s,h,d]
__device__ float g_cos [S_*(DH_/2)];
__device__ float g_sin [S_*(DH_/2)];

// =====================================================================
// helpers
// =====================================================================
__device__ __forceinline__ uint32_t smem_u32(const void* p) {
    uint32_t a;
    asm("{ .reg .u64 t; cvta.to.shared.u64 t, %1; cvt.u32.u64 %0, t; }"
        : "=r"(a) : "l"(p));
    return a;
}

__device__ __forceinline__ uint32_t pack2(__nv_bfloat16 a, __nv_bfloat16 b) {
    uint16_t x = *(uint16_t*)&a, y = *(uint16_t*)&b;
    return (uint32_t)x | ((uint32_t)y << 16);
}

#define LDSM_X4(r0, r1, r2, r3, addr) \
    asm volatile("ldmatrix.sync.aligned.m8n8.x4.shared.b16 {%0,%1,%2,%3}, [%4];" \
                 : "=r"(r0), "=r"(r1), "=r"(r2), "=r"(r3) : "r"(addr))

#define MMA16816(d, a0, a1, a2, a3, b0, b1) \
    asm volatile("mma.sync.aligned.m16n8k16.row.col.f32.bf16.bf16.f32 " \
                 "{%0,%1,%2,%3}, {%4,%5,%6,%7}, {%8,%9}, {%0,%1,%2,%3};" \
                 : "+f"((d)[0]), "+f"((d)[1]), "+f"((d)[2]), "+f"((d)[3]) \
                 : "r"(a0), "r"(a1), "r"(a2), "r"(a3), "r"(b0), "r"(b1))

// =====================================================================
// mma.sync bf16 GEMM (3-term fp32 emulation): C[M,N] = A[M,K] @ W[N,K]^T + bias
// CTA 128x128, warp tile 32x64, K-chunk 32, double-buffered smem.
// smem per stage: Ahi[128][40] Alo Bhi Blo (bf16, 80B row stride).
// =====================================================================
#define ASTRIDE 40
#define ARR_B   (128 * ASTRIDE * 2)      // 10240 bytes per array
#define STAGE_B (4 * ARR_B)              // 40960
#define GEMM_DYN (2 * STAGE_B)           // 81920

__global__ __launch_bounds__(256, 2)
void gemm_mma_kernel(const float* __restrict__ A, const float* __restrict__ W,
                     const float* __restrict__ bias, float* __restrict__ C,
                     int K, int N) {
    extern __shared__ char dsm[];
    const int tid  = threadIdx.x;
    const int lane = tid & 31, wid = tid >> 5;
    const int wm = wid & 3;          // 4 m-slots of 32 rows
    const int wn = wid >> 2;         // 2 n-slots of 64 cols
    const uint32_t sbase = smem_u32(dsm);

    const float* Ab = A + (size_t)blockIdx.y * 128 * K;
    const float* Wb = W + (size_t)blockIdx.x * 128 * K;

    float acc[2][8][4];
    #pragma unroll
    for (int mt = 0; mt < 2; ++mt)
        #pragma unroll
        for (int nt = 0; nt < 8; ++nt)
            #pragma unroll
            for (int j = 0; j < 4; ++j) acc[mt][nt][j] = 0.f;

    // ldmatrix row/col pieces (per lane)
    const int aRow = wm * 32 + (lane & 7) + ((lane >> 3) & 1) * 8;  // + mt*16
    const int aCol = (lane >> 4) * 8;                               // + kp*16
    const int bRow = wn * 64 + (lane & 7) + ((lane >> 4) & 1) * 8;  // + np*16
    const int bCol = ((lane >> 3) & 1) * 8;                         // + kp*16

    const int fr  = (tid >> 3);      // 0..31 base row for fills
    const int fc4 = (tid & 7);       // float4 index within 32-float chunk

    const int kc = K >> 5;

    // ---- fill one stage with chunk c (A and B tiles, hi/lo split) ----
    auto fill = [&](int stage, int c) {
        const float* Ak = Ab + c * 32;
        const float* Wk = Wb + c * 32;
        char* st = dsm + stage * STAGE_B;
        __nv_bfloat16* Ah = (__nv_bfloat16*)st;
        __nv_bfloat16* Al = (__nv_bfloat16*)(st + ARR_B);
        __nv_bfloat16* Bh = (__nv_bfloat16*)(st + 2 * ARR_B);
        __nv_bfloat16* Bl = (__nv_bfloat16*)(st + 3 * ARR_B);
        #pragma unroll
        for (int i = 0; i < 4; ++i) {
            int r = fr + i * 32;
            float4 v = *(const float4*)(Ak + (size_t)r * K + fc4 * 4);
            __nv_bfloat16 h0 = __float2bfloat16_rn(v.x);
            __nv_bfloat16 h1 = __float2bfloat16_rn(v.y);
            __nv_bfloat16 h2 = __float2bfloat16_rn(v.z);
            __nv_bfloat16 h3 = __float2bfloat16_rn(v.w);
            float l0 = v.x - __bfloat162float(h0);
            float l1 = v.y - __bfloat162float(h1);
            float l2 = v.z - __bfloat162float(h2);
            float l3 = v.w - __bfloat162float(h3);
            uint2 hi = make_uint2(pack2(h0, h1), pack2(h2, h3));
            uint2 lo = make_uint2(pack2(__float2bfloat16_rn(l0), __float2bfloat16_rn(l1)),
                                  pack2(__float2bfloat16_rn(l2), __float2bfloat16_rn(l3)));
            *(uint2*)(Ah + r * ASTRIDE + fc4 * 4) = hi;
            *(uint2*)(Al + r * ASTRIDE + fc4 * 4) = lo;

            float4 w = *(const float4*)(Wk + (size_t)r * K + fc4 * 4);
            __nv_bfloat16 g0 = __float2bfloat16_rn(w.x);
            __nv_bfloat16 g1 = __float2bfloat16_rn(w.y);
            __nv_bfloat16 g2 = __float2bfloat16_rn(w.z);
            __nv_bfloat16 g3 = __float2bfloat16_rn(w.w);
            float m0 = w.x - __bfloat162float(g0);
            float m1 = w.y - __bfloat162float(g1);
            float m2 = w.z - __bfloat162float(g2);
            float m3 = w.w - __bfloat162float(g3);
            uint2 whi = make_uint2(pack2(g0, g1), pack2(g2, g3));
            uint2 wlo = make_uint2(pack2(__float2bfloat16_rn(m0), __float2bfloat16_rn(m1)),
                                   pack2(__float2bfloat16_rn(m2), __float2bfloat16_rn(m3)));
            *(uint2*)(Bh + r * ASTRIDE + fc4 * 4) = whi;
            *(uint2*)(Bl + r * ASTRIDE + fc4 * 4) = wlo;
        }
    };

    fill(0, 0);
    __syncthreads();

    for (int c = 0; c < kc; ++c) {
        if (c + 1 < kc) fill((c + 1) & 1, c + 1);

        const uint32_t sa = sbase + (uint32_t)(c & 1) * STAGE_B;
        const uint32_t aBase = sa + (aRow * ASTRIDE + aCol) * 2;
        const uint32_t bBase = sa + 2 * ARR_B + (bRow * ASTRIDE + bCol) * 2;

        #pragma unroll
        for (int kp = 0; kp < 2; ++kp) {
            uint32_t ah[2][4], al[2][4];
            #pragma unroll
            for (int mt = 0; mt < 2; ++mt) {
                uint32_t ad = aBase + (mt * 16 * ASTRIDE + kp * 16) * 2;
                LDSM_X4(ah[mt][0], ah[mt][1], ah[mt][2], ah[mt][3], ad);
                LDSM_X4(al[mt][0], al[mt][1], al[mt][2], al[mt][3], ad + ARR_B);
            }
            #pragma unroll
            for (int np = 0; np < 4; ++np) {
                uint32_t bh[4], bl[4];
                uint32_t bd = bBase + (np * 16 * ASTRIDE + kp * 16) * 2;
                LDSM_X4(bh[0], bh[1], bh[2], bh[3], bd);
                LDSM_X4(bl[0], bl[1], bl[2], bl[3], bd + ARR_B);
                const int nt = np * 2;
                // term hi*hi (4 independent accumulators)
                MMA16816(acc[0][nt],   ah[0][0], ah[0][1], ah[0][2], ah[0][3], bh[0], bh[1]);
                MMA16816(acc[0][nt+1], ah[0][0], ah[0][1], ah[0][2], ah[0][3], bh[2], bh[3]);
                MMA16816(acc[1][nt],   ah[1][0], ah[1][1], ah[1][2], ah[1][3], bh[0], bh[1]);
                MMA16816(acc[1][nt+1], ah[1][0], ah[1][1], ah[1][2], ah[1][3], bh[2], bh[3]);
                // term hi*lo
                MMA16816(acc[0][nt],   ah[0][0], ah[0][1], ah[0][2], ah[0][3], bl[0], bl[1]);
                MMA16816(acc[0][nt+1], ah[0][0], ah[0][1], ah[0][2], ah[0][3], bl[2], bl[3]);
                MMA16816(acc[1][nt],   ah[1][0], ah[1][1], ah[1][2], ah[1][3], bl[0], bl[1]);
                MMA16816(acc[1][nt+1], ah[1][0], ah[1][1], ah[1][2], ah[1][3], bl[2], bl[3]);
                // term lo*hi
                MMA16816(acc[0][nt],   al[0][0], al[0][1], al[0][2], al[0][3], bh[0], bh[1]);
                MMA16816(acc[0][nt+1], al[0][0], al[0][1], al[0][2], al[0][3], bh[2], bh[3]);
                MMA16816(acc[1][nt],   al[1][0], al[1][1], al[1][2], al[1][3], bh[0], bh[1]);
                MMA16816(acc[1][nt+1], al[1][0], al[1][1], al[1][2], al[1][3], bh[2], bh[3]);
            }
        }
        __syncthreads();
    }

    // epilogue: write C + bias
    const int r0 = blockIdx.y * 128 + wm * 32 + (lane >> 2);
    const int c0 = blockIdx.x * 128 + wn * 64 + (lane & 3) * 2;
    #pragma unroll
    for (int mt = 0; mt < 2; ++mt) {
        #pragma unroll
        for (int nt = 0; nt < 8; ++nt) {
            int row = r0 + mt * 16;
            int col = c0 + nt * 8;
            float b0 = __ldg(bias + col), b1 = __ldg(bias + col + 1);
            float2 o0 = make_float2(acc[mt][nt][0] + b0, acc[mt][nt][1] + b1);
            float2 o1 = make_float2(acc[mt][nt][2] + b0, acc[mt][nt][3] + b1);
            *(float2*)(C + (size_t)row * N + col)       = o0;
            *(float2*)(C + (size_t)(row + 8) * N + col) = o1;
        }
    }
}

// ---------------- RoPE table (fp32, matches jnp op ordering) ----------------
__global__ void rope_table_kernel() {
    int idx = blockIdx.x * blockDim.x + threadIdx.x;
    if (idx >= S_*(DH_/2)) return;
    int s = idx >> 6;
    int i = idx & 63;
    float expo = (float)(2*i) / 128.0f;
    float inv  = 1.0f / powf(10000.0f, expo);
    float ang  = (float)s * inv;
    g_cos[idx] = cosf(ang);
    g_sin[idx] = sinf(ang);
}

// ---------------- RoPE on q (in place) ----------------
__global__ void rope_q_kernel() {
    int idx = blockIdx.x * blockDim.x + threadIdx.x;
    if (idx >= M_*H_*64) return;
    int i    = idx & 63;
    int qrow = idx >> 6;                  // (b*S+s)*H + h
    int s    = (qrow >> 4) & (S_-1);
    float* qp = g_q + (size_t)qrow * DH_;
    float x1 = qp[i], x2 = qp[i+64];
    float cv = g_cos[s*64 + i], sv = g_sin[s*64 + i];
    qp[i]    = x1*cv - x2*sv;
    qp[i+64] = x2*cv + x1*sv;
}

// ---------------- split kv -> k (RoPE), v ----------------
__global__ void kv_split_kernel() {
    int idx = blockIdx.x * blockDim.x + threadIdx.x;
    if (idx >= M_*64) return;
    int i   = idx & 63;
    int row = idx >> 6;
    int s   = row & (S_-1);
    const float* kvr = g_kv + (size_t)row * 256;
    float x1 = kvr[i], x2 = kvr[i+64];
    float cv = g_cos[s*64 + i], sv = g_sin[s*64 + i];
    g_k[(size_t)row*DH_ + i]      = x1*cv - x2*sv;
    g_k[(size_t)row*DH_ + i + 64] = x2*cv + x1*sv;
    g_v[(size_t)row*DH_ + i]      = kvr[128 + i];
    g_v[(size_t)row*DH_ + i + 64] = kvr[128 + i + 64];
}

// ---------------- flash attention (causal, MQA) ----------------
#define QS_STRIDE 132
#define KT_STRIDE 68
#define PS_STRIDE 68
#define FA_SMEM_FLOATS (64*QS_STRIDE + 128*KT_STRIDE + 64*PS_STRIDE)
#define FA_SMEM_BYTES  (FA_SMEM_FLOATS * 4)

__global__ __launch_bounds__(256, 2)
void flash_attn_kernel() {
    extern __shared__ float sm[];
    float* Qs = sm;                      // [64][132]
    float* KT = Qs + 64*QS_STRIDE;       // K: [128][68] transposed / V: [64][132]
    float* Ps = KT + 128*KT_STRIDE;      // [64][68]

    const int tid = threadIdx.x;
    const int tx = tid & 15, ty = tid >> 4;
    const int qt = blockIdx.x;
    const int b  = blockIdx.y >> 4;
    const int h  = blockIdx.y & 15;

    const float* qbase = g_q + (((size_t)(b*S_ + qt*64))*H_ + h) * DH_;
    #pragma unroll
    for (int it = 0; it < 8; ++it) {
        int f4 = tid + it*256;
        int r = f4 >> 5, c4 = f4 & 31;
        float4 v = *(const float4*)(qbase + (size_t)r*(H_*DH_) + c4*4);
        v.x *= SCALE_; v.y *= SCALE_; v.z *= SCALE_; v.w *= SCALE_;
        *(float4*)&Qs[r*QS_STRIDE + c4*4] = v;
    }

    float m_i[4], l_i[4], acc[4][8];
    #pragma unroll
    for (int i = 0; i < 4; ++i) {
        m_i[i] = -1e30f; l_i[i] = 0.f;
        #pragma unroll
        for (int j = 0; j < 8; ++j) acc[i][j] = 0.f;
    }
    __syncthreads();

    for (int kt = 0; kt <= qt; ++kt) {
        const float* kbase = g_k + ((size_t)b*S_ + kt*64) * DH_;
        #pragma unroll
        for (int it = 0; it < 8; ++it) {
            int f4 = tid + it*256;
            int d4 = f4 >> 6, kr = f4 & 63;
            float4 v = *(const float4*)(kbase + (size_t)kr*DH_ + d4*4);
            KT[(d4*4+0)*KT_STRIDE + kr] = v.x;
            KT[(d4*4+1)*KT_STRIDE + kr] = v.y;
            KT[(d4*4+2)*KT_STRIDE + kr] = v.z;
            KT[(d4*4+3)*KT_STRIDE + kr] = v.w;
        }
        __syncthreads();

        float s[4][4];
        #pragma unroll
        for (int i = 0; i < 4; ++i)
            #pragma unroll
            for (int j = 0; j < 4; ++j) s[i][j] = 0.f;

        #pragma unroll 4
        for (int d4 = 0; d4 < 32; ++d4) {
            float4 a[4], bb[4];
            #pragma unroll
            for (int i = 0; i < 4; ++i)
                a[i] = *(const float4*)&Qs[(ty*4+i)*QS_STRIDE + d4*4];
            #pragma unroll
            for (int u = 0; u < 4; ++u)
                bb[u] = *(const float4*)&KT[(d4*4+u)*KT_STRIDE + tx*4];
            #pragma unroll
            for (int i = 0; i < 4; ++i) {
                s[i][0] = fmaf(a[i].x, bb[0].x, s[i][0]);
                s[i][1] = fmaf(a[i].x, bb[0].y, s[i][1]);
                s[i][2] = fmaf(a[i].x, bb[0].z, s[i][2]);
                s[i][3] = fmaf(a[i].x, bb[0].w, s[i][3]);
                s[i][0] = fmaf(a[i].y, bb[1].x, s[i][0]);
                s[i][1] = fmaf(a[i].y, bb[1].y, s[i][1]);
                s[i][2] = fmaf(a[i].y, bb[1].z, s[i][2]);
                s[i][3] = fmaf(a[i].y, bb[1].w, s[i][3]);
                s[i][0] = fmaf(a[i].z, bb[2].x, s[i][0]);
                s[i][1] = fmaf(a[i].z, bb[2].y, s[i][1]);
                s[i][2] = fmaf(a[i].z, bb[2].z, s[i][2]);
                s[i][3] = fmaf(a[i].z, bb[2].w, s[i][3]);
                s[i][0] = fmaf(a[i].w, bb[3].x, s[i][0]);
                s[i][1] = fmaf(a[i].w, bb[3].y, s[i][1]);
                s[i][2] = fmaf(a[i].w, bb[3].z, s[i][2]);
                s[i][3] = fmaf(a[i].w, bb[3].w, s[i][3]);
            }
        }

        if (kt == qt) {
            #pragma unroll
            for (int i = 0; i < 4; ++i)
                #pragma unroll
                for (int j = 0; j < 4; ++j)
                    if (tx*4+j > ty*4+i) s[i][j] = -1e30f;
        }

        #pragma unroll
        for (int i = 0; i < 4; ++i) {
            float rm = fmaxf(fmaxf(s[i][0], s[i][1]), fmaxf(s[i][2], s[i][3]));
            rm = fmaxf(rm, __shfl_xor_sync(0xffffffffu, rm, 1, 16));
            rm = fmaxf(rm, __shfl_xor_sync(0xffffffffu, rm, 2, 16));
            rm = fmaxf(rm, __shfl_xor_sync(0xffffffffu, rm, 4, 16));
            rm = fmaxf(rm, __shfl_xor_sync(0xffffffffu, rm, 8, 16));
            float mn   = fmaxf(m_i[i], rm);
            float corr = __expf(m_i[i] - mn);
            float rs = 0.f;
            #pragma unroll
            for (int j = 0; j < 4; ++j) {
                float p = __expf(s[i][j] - mn);
                Ps[(ty*4+i)*PS_STRIDE + tx*4 + j] = p;
                rs += p;
            }
            rs += __shfl_xor_sync(0xffffffffu, rs, 1, 16);
            rs += __shfl_xor_sync(0xffffffffu, rs, 2, 16);
            rs += __shfl_xor_sync(0xffffffffu, rs, 4, 16);
            rs += __shfl_xor_sync(0xffffffffu, rs, 8, 16);
            l_i[i] = l_i[i]*corr + rs;
            m_i[i] = mn;
            #pragma unroll
            for (int j = 0; j < 8; ++j) acc[i][j] *= corr;
        }
        __syncthreads();

        const float* vbase = g_v + ((size_t)b*S_ + kt*64) * DH_;
        #pragma unroll
        for (int it = 0; it < 8; ++it) {
            int f4 = tid + it*256;
            int r = f4 >> 5, c4 = f4 & 31;
            *(float4*)&KT[r*QS_STRIDE + c4*4] =
                *(const float4*)(vbase + (size_t)r*DH_ + c4*4);
        }
        __syncthreads();

        #pragma unroll 4
        for (int kk = 0; kk < 64; ++kk) {
            float4 v0 = *(const float4*)&KT[kk*QS_STRIDE + tx*8];
            float4 v1 = *(const float4*)&KT[kk*QS_STRIDE + tx*8 + 4];
            #pragma unroll
            for (int i = 0; i < 4; ++i) {
                float p = Ps[(ty*4+i)*PS_STRIDE + kk];
                acc[i][0] = fmaf(p, v0.x, acc[i][0]);
                acc[i][1] = fmaf(p, v0.y, acc[i][1]);
                acc[i][2] = fmaf(p, v0.z, acc[i][2]);
                acc[i][3] = fmaf(p, v0.w, acc[i][3]);
                acc[i][4] = fmaf(p, v1.x, acc[i][4]);
                acc[i][5] = fmaf(p, v1.y, acc[i][5]);
                acc[i][6] = fmaf(p, v1.z, acc[i][6]);
                acc[i][7] = fmaf(p, v1.w, acc[i][7]);
            }
        }
        __syncthreads();
    }

    #pragma unroll
    for (int i = 0; i < 4; ++i) {
        float inv = 1.0f / l_i[i];
        int row = qt*64 + ty*4 + i;
        float* outp = g_attn + (((size_t)(b*S_ + row))*H_ + h) * DH_ + tx*8;
        float4 o0 = make_float4(acc[i][0]*inv, acc[i][1]*inv, acc[i][2]*inv, acc[i][3]*inv);
        float4 o1 = make_float4(acc[i][4]*inv, acc[i][5]*inv, acc[i][6]*inv, acc[i][7]*inv);
        *(float4*)(outp)     = o0;
        *(float4*)(outp + 4) = o1;
    }
}

// ---------------- launch ----------------
extern "C" void kernel_launch(void* const* d_in, const int* in_sizes, int n_in,
                              void* d_out, int out_size) {
    const float* x        = (const float*)d_in[0];
    const float* q_weight = (const float*)d_in[1];
    const float* q_bias   = (const float*)d_in[2];
    const float* kv_weight= (const float*)d_in[3];
    const float* kv_bias  = (const float*)d_in[4];
    const float* o_weight = (const float*)d_in[5];
    const float* o_bias   = (const float*)d_in[6];
    float* out = (float*)d_out;

    float *pq, *pkv, *pattn;
    cudaGetSymbolAddress((void**)&pq,    g_q);
    cudaGetSymbolAddress((void**)&pkv,   g_kv);
    cudaGetSymbolAddress((void**)&pattn, g_attn);

    cudaFuncSetAttribute(flash_attn_kernel,
                         cudaFuncAttributeMaxDynamicSharedMemorySize, FA_SMEM_BYTES);
    cudaFuncSetAttribute(gemm_mma_kernel,
                         cudaFuncAttributeMaxDynamicSharedMemorySize, GEMM_DYN);

    // 1. RoPE tables
    rope_table_kernel<<<(S_*64 + 255)/256, 256>>>();
    // 2. Q projection (mma.sync bf16 x3)
    gemm_mma_kernel<<<dim3(D_/128, M_/128), 256, GEMM_DYN>>>(
        x, q_weight, q_bias, pq, D_, D_);
    // 3. KV projection
    gemm_mma_kernel<<<dim3(256/128, M_/128), 256, GEMM_DYN>>>(
        x, kv_weight, kv_bias, pkv, D_, 256);
    // 4. RoPE on q
    rope_q_kernel<<<(M_*H_*64 + 255)/256, 256>>>();
    // 5. split kv, RoPE on k
    kv_split_kernel<<<(M_*64 + 255)/256, 256>>>();
    // 6. attention
    flash_attn_kernel<<<dim3(S_/64, B_*H_), 256, FA_SMEM_BYTES>>>();
    // 7. O projection -> d_out
    gemm_mma_kernel<<<dim3(D_/128, M_/128), 256, GEMM_DYN>>>(
        pattn, o_weight, o_bias, out, D_, D_);
}

// round 5
// speedup vs baseline: 2.7611x; 1.9020x over previous
#include <cuda_runtime.h>
#include <cuda_bf16.h>
#include <math.h>
#include <stdint.h>

#define B_  2
#define S_  2048
#define D_  2048
#define H_  16
#define DH_ 128
#define M_  (B_*S_)          // 4096 rows (b*S+s)
#define SCALE_ 0.08838834764831845f  // 1/sqrt(128)

// ---------------- scratch (device globals; no allocations) ----------------
__device__ float g_q   [(size_t)M_*H_*DH_];   // fp32 Q proj output
__device__ float g_kv  [(size_t)M_*2*DH_];    // fp32 KV proj output
__device__ float g_attn[(size_t)M_*H_*DH_];   // attention output [b,s,h,d]
__device__ float g_cos [S_*(DH_/2)];
__device__ float g_sin [S_*(DH_/2)];
// bf16 hi/lo operands for tensorized attention
__device__ __nv_bfloat16 g_qh[(size_t)M_*H_*DH_];
__device__ __nv_bfloat16 g_ql[(size_t)M_*H_*DH_];
__device__ __nv_bfloat16 g_kh[(size_t)M_*DH_];
__device__ __nv_bfloat16 g_kl[(size_t)M_*DH_];
__device__ __nv_bfloat16 g_vh[(size_t)M_*DH_];
__device__ __nv_bfloat16 g_vl[(size_t)M_*DH_];

// =====================================================================
// helpers
// =====================================================================
__device__ __forceinline__ uint32_t smem_u32(const void* p) {
    uint32_t a;
    asm("{ .reg .u64 t; cvta.to.shared.u64 t, %1; cvt.u32.u64 %0, t; }"
        : "=r"(a) : "l"(p));
    return a;
}

__device__ __forceinline__ uint32_t pack2(__nv_bfloat16 a, __nv_bfloat16 b) {
    uint16_t x = *(uint16_t*)&a, y = *(uint16_t*)&b;
    return (uint32_t)x | ((uint32_t)y << 16);
}

#define LDSM_X4(r0, r1, r2, r3, addr) \
    asm volatile("ldmatrix.sync.aligned.m8n8.x4.shared.b16 {%0,%1,%2,%3}, [%4];" \
                 : "=r"(r0), "=r"(r1), "=r"(r2), "=r"(r3) : "r"(addr))

#define LDSM_X4T(r0, r1, r2, r3, addr) \
    asm volatile("ldmatrix.sync.aligned.m8n8.x4.trans.shared.b16 {%0,%1,%2,%3}, [%4];" \
                 : "=r"(r0), "=r"(r1), "=r"(r2), "=r"(r3) : "r"(addr))

#define MMA16816(d, a0, a1, a2, a3, b0, b1) \
    asm volatile("mma.sync.aligned.m16n8k16.row.col.f32.bf16.bf16.f32 " \
                 "{%0,%1,%2,%3}, {%4,%5,%6,%7}, {%8,%9}, {%0,%1,%2,%3};" \
                 : "+f"((d)[0]), "+f"((d)[1]), "+f"((d)[2]), "+f"((d)[3]) \
                 : "r"(a0), "r"(a1), "r"(a2), "r"(a3), "r"(b0), "r"(b1))

// fast exp on fma/alu pipes (no MUFU). x <= 0 expected; rel err ~3e-6.
__device__ __forceinline__ float fexp(float x) {
    x = fmaxf(x, -87.0f);
    float y = x * 1.44269504f;
    float i = rintf(y);
    float f = (y - i) * 0.69314718f;         // |f| <= 0.3466
    float p = 1.0f + f*(1.0f + f*(0.5f + f*(0.166666667f + f*(0.0416666667f + f*0.00833333f))));
    int e = (int)i;
    float sc = __int_as_float((e + 127) << 23);
    return p * sc;
}

// =====================================================================
// mma.sync bf16 GEMM (3-term fp32 emulation): C[M,N] = A[M,K] @ W[N,K]^T + bias
// =====================================================================
#define ASTRIDE 40
#define ARR_B   (128 * ASTRIDE * 2)      // 10240 bytes per array
#define STAGE_B (4 * ARR_B)              // 40960
#define GEMM_DYN (2 * STAGE_B)           // 81920

__global__ __launch_bounds__(256, 2)
void gemm_mma_kernel(const float* __restrict__ A, const float* __restrict__ W,
                     const float* __restrict__ bias, float* __restrict__ C,
                     int K, int N) {
    extern __shared__ char dsm[];
    const int tid  = threadIdx.x;
    const int lane = tid & 31, wid = tid >> 5;
    const int wm = wid & 3;
    const int wn = wid >> 2;
    const uint32_t sbase = smem_u32(dsm);

    const float* Ab = A + (size_t)blockIdx.y * 128 * K;
    const float* Wb = W + (size_t)blockIdx.x * 128 * K;

    float acc[2][8][4];
    #pragma unroll
    for (int mt = 0; mt < 2; ++mt)
        #pragma unroll
        for (int nt = 0; nt < 8; ++nt)
            #pragma unroll
            for (int j = 0; j < 4; ++j) acc[mt][nt][j] = 0.f;

    const int aRow = wm * 32 + (lane & 7) + ((lane >> 3) & 1) * 8;
    const int aCol = (lane >> 4) * 8;
    const int bRow = wn * 64 + (lane & 7) + ((lane >> 4) & 1) * 8;
    const int bCol = ((lane >> 3) & 1) * 8;

    const int fr  = (tid >> 3);
    const int fc4 = (tid & 7);
    const int kc = K >> 5;

    auto fill = [&](int stage, int c) {
        const float* Ak = Ab + c * 32;
        const float* Wk = Wb + c * 32;
        char* st = dsm + stage * STAGE_B;
        __nv_bfloat16* Ah = (__nv_bfloat16*)st;
        __nv_bfloat16* Al = (__nv_bfloat16*)(st + ARR_B);
        __nv_bfloat16* Bh = (__nv_bfloat16*)(st + 2 * ARR_B);
        __nv_bfloat16* Bl = (__nv_bfloat16*)(st + 3 * ARR_B);
        #pragma unroll
        for (int i = 0; i < 4; ++i) {
            int r = fr + i * 32;
            float4 v = *(const float4*)(Ak + (size_t)r * K + fc4 * 4);
            __nv_bfloat16 h0 = __float2bfloat16_rn(v.x);
            __nv_bfloat16 h1 = __float2bfloat16_rn(v.y);
            __nv_bfloat16 h2 = __float2bfloat16_rn(v.z);
            __nv_bfloat16 h3 = __float2bfloat16_rn(v.w);
            float l0 = v.x - __bfloat162float(h0);
            float l1 = v.y - __bfloat162float(h1);
            float l2 = v.z - __bfloat162float(h2);
            float l3 = v.w - __bfloat162float(h3);
            uint2 hi = make_uint2(pack2(h0, h1), pack2(h2, h3));
            uint2 lo = make_uint2(pack2(__float2bfloat16_rn(l0), __float2bfloat16_rn(l1)),
                                  pack2(__float2bfloat16_rn(l2), __float2bfloat16_rn(l3)));
            *(uint2*)(Ah + r * ASTRIDE + fc4 * 4) = hi;
            *(uint2*)(Al + r * ASTRIDE + fc4 * 4) = lo;

            float4 w = *(const float4*)(Wk + (size_t)r * K + fc4 * 4);
            __nv_bfloat16 g0 = __float2bfloat16_rn(w.x);
            __nv_bfloat16 g1 = __float2bfloat16_rn(w.y);
            __nv_bfloat16 g2 = __float2bfloat16_rn(w.z);
            __nv_bfloat16 g3 = __float2bfloat16_rn(w.w);
            float m0 = w.x - __bfloat162float(g0);
            float m1 = w.y - __bfloat162float(g1);
            float m2 = w.z - __bfloat162float(g2);
            float m3 = w.w - __bfloat162float(g3);
            uint2 whi = make_uint2(pack2(g0, g1), pack2(g2, g3));
            uint2 wlo = make_uint2(pack2(__float2bfloat16_rn(m0), __float2bfloat16_rn(m1)),
                                   pack2(__float2bfloat16_rn(m2), __float2bfloat16_rn(m3)));
            *(uint2*)(Bh + r * ASTRIDE + fc4 * 4) = whi;
            *(uint2*)(Bl + r * ASTRIDE + fc4 * 4) = wlo;
        }
    };

    fill(0, 0);
    __syncthreads();

    for (int c = 0; c < kc; ++c) {
        if (c + 1 < kc) fill((c + 1) & 1, c + 1);

        const uint32_t sa = sbase + (uint32_t)(c & 1) * STAGE_B;
        const uint32_t aBase = sa + (aRow * ASTRIDE + aCol) * 2;
        const uint32_t bBase = sa + 2 * ARR_B + (bRow * ASTRIDE + bCol) * 2;

        #pragma unroll
        for (int kp = 0; kp < 2; ++kp) {
            uint32_t ah[2][4], al[2][4];
            #pragma unroll
            for (int mt = 0; mt < 2; ++mt) {
                uint32_t ad = aBase + (mt * 16 * ASTRIDE + kp * 16) * 2;
                LDSM_X4(ah[mt][0], ah[mt][1], ah[mt][2], ah[mt][3], ad);
                LDSM_X4(al[mt][0], al[mt][1], al[mt][2], al[mt][3], ad + ARR_B);
            }
            #pragma unroll
            for (int np = 0; np < 4; ++np) {
                uint32_t bh[4], bl[4];
                uint32_t bd = bBase + (np * 16 * ASTRIDE + kp * 16) * 2;
                LDSM_X4(bh[0], bh[1], bh[2], bh[3], bd);
                LDSM_X4(bl[0], bl[1], bl[2], bl[3], bd + ARR_B);
                const int nt = np * 2;
                MMA16816(acc[0][nt],   ah[0][0], ah[0][1], ah[0][2], ah[0][3], bh[0], bh[1]);
                MMA16816(acc[0][nt+1], ah[0][0], ah[0][1], ah[0][2], ah[0][3], bh[2], bh[3]);
                MMA16816(acc[1][nt],   ah[1][0], ah[1][1], ah[1][2], ah[1][3], bh[0], bh[1]);
                MMA16816(acc[1][nt+1], ah[1][0], ah[1][1], ah[1][2], ah[1][3], bh[2], bh[3]);
                MMA16816(acc[0][nt],   ah[0][0], ah[0][1], ah[0][2], ah[0][3], bl[0], bl[1]);
                MMA16816(acc[0][nt+1], ah[0][0], ah[0][1], ah[0][2], ah[0][3], bl[2], bl[3]);
                MMA16816(acc[1][nt],   ah[1][0], ah[1][1], ah[1][2], ah[1][3], bl[0], bl[1]);
                MMA16816(acc[1][nt+1], ah[1][0], ah[1][1], ah[1][2], ah[1][3], bl[2], bl[3]);
                MMA16816(acc[0][nt],   al[0][0], al[0][1], al[0][2], al[0][3], bh[0], bh[1]);
                MMA16816(acc[0][nt+1], al[0][0], al[0][1], al[0][2], al[0][3], bh[2], bh[3]);
                MMA16816(acc[1][nt],   al[1][0], al[1][1], al[1][2], al[1][3], bh[0], bh[1]);
                MMA16816(acc[1][nt+1], al[1][0], al[1][1], al[1][2], al[1][3], bh[2], bh[3]);
            }
        }
        __syncthreads();
    }

    const int r0 = blockIdx.y * 128 + wm * 32 + (lane >> 2);
    const int c0 = blockIdx.x * 128 + wn * 64 + (lane & 3) * 2;
    #pragma unroll
    for (int mt = 0; mt < 2; ++mt) {
        #pragma unroll
        for (int nt = 0; nt < 8; ++nt) {
            int row = r0 + mt * 16;
            int col = c0 + nt * 8;
            float b0 = __ldg(bias + col), b1 = __ldg(bias + col + 1);
            float2 o0 = make_float2(acc[mt][nt][0] + b0, acc[mt][nt][1] + b1);
            float2 o1 = make_float2(acc[mt][nt][2] + b0, acc[mt][nt][3] + b1);
            *(float2*)(C + (size_t)row * N + col)       = o0;
            *(float2*)(C + (size_t)(row + 8) * N + col) = o1;
        }
    }
}

// ---------------- RoPE table ----------------
__global__ void rope_table_kernel() {
    int idx = blockIdx.x * blockDim.x + threadIdx.x;
    if (idx >= S_*(DH_/2)) return;
    int s = idx >> 6;
    int i = idx & 63;
    float expo = (float)(2*i) / 128.0f;
    float inv  = 1.0f / powf(10000.0f, expo);
    float ang  = (float)s * inv;
    g_cos[idx] = cosf(ang);
    g_sin[idx] = sinf(ang);
}

// ---------------- RoPE on q -> scaled bf16 hi/lo ----------------
__global__ void rope_q_kernel() {
    int idx = blockIdx.x * blockDim.x + threadIdx.x;
    if (idx >= M_*H_*64) return;
    int i    = idx & 63;
    int qrow = idx >> 6;                  // (b*S+s)*H + h
    int s    = (qrow >> 4) & (S_-1);
    const float* qp = g_q + (size_t)qrow * DH_;
    float x1 = qp[i], x2 = qp[i+64];
    float cv = g_cos[s*64 + i], sv = g_sin[s*64 + i];
    float y1 = (x1*cv - x2*sv) * SCALE_;
    float y2 = (x2*cv + x1*sv) * SCALE_;
    size_t base = (size_t)qrow * DH_;
    __nv_bfloat16 h1 = __float2bfloat16_rn(y1);
    __nv_bfloat16 h2 = __float2bfloat16_rn(y2);
    g_qh[base + i]      = h1;
    g_qh[base + i + 64] = h2;
    g_ql[base + i]      = __float2bfloat16_rn(y1 - __bfloat162float(h1));
    g_ql[base + i + 64] = __float2bfloat16_rn(y2 - __bfloat162float(h2));
}

// ---------------- split kv -> k (RoPE) hi/lo, v hi/lo ----------------
__global__ void kv_split_kernel() {
    int idx = blockIdx.x * blockDim.x + threadIdx.x;
    if (idx >= M_*64) return;
    int i   = idx & 63;
    int row = idx >> 6;
    int s   = row & (S_-1);
    const float* kvr = g_kv + (size_t)row * 256;
    float x1 = kvr[i], x2 = kvr[i+64];
    float cv = g_cos[s*64 + i], sv = g_sin[s*64 + i];
    float k1 = x1*cv - x2*sv;
    float k2 = x2*cv + x1*sv;
    float v1 = kvr[128 + i];
    float v2 = kvr[128 + i + 64];
    size_t base = (size_t)row * DH_;
    __nv_bfloat16 kh1 = __float2bfloat16_rn(k1);
    __nv_bfloat16 kh2 = __float2bfloat16_rn(k2);
    __nv_bfloat16 vh1 = __float2bfloat16_rn(v1);
    __nv_bfloat16 vh2 = __float2bfloat16_rn(v2);
    g_kh[base + i]      = kh1;
    g_kh[base + i + 64] = kh2;
    g_kl[base + i]      = __float2bfloat16_rn(k1 - __bfloat162float(kh1));
    g_kl[base + i + 64] = __float2bfloat16_rn(k2 - __bfloat162float(kh2));
    g_vh[base + i]      = vh1;
    g_vh[base + i + 64] = vh2;
    g_vl[base + i]      = __float2bfloat16_rn(v1 - __bfloat162float(vh1));
    g_vl[base + i + 64] = __float2bfloat16_rn(v2 - __bfloat162float(vh2));
}

// =====================================================================
// tensorized flash attention (causal MQA): 128 q-rows/CTA, 64-col k-tiles
// 8 warps x m16; QK^T and PV via mma.sync bf16 3-term emulation.
// =====================================================================
#define FA_STR  136                          // smem row stride (bf16 elems)
#define QH_OFF  0
#define QL_OFF  (128*FA_STR*2)
#define KH_OFF  (2*128*FA_STR*2)
#define KL_OFF  (KH_OFF + 64*FA_STR*2)
#define VH_OFF  (KL_OFF + 64*FA_STR*2)
#define VL_OFF  (VH_OFF + 64*FA_STR*2)
#define FA_BYTES (VL_OFF + 64*FA_STR*2)      // 139264

__global__ __launch_bounds__(256, 1)
void flash_attn_mma_kernel() {
    extern __shared__ char sm2[];
    const int tid  = threadIdx.x;
    const int lane = tid & 31, w = tid >> 5;
    const int b  = blockIdx.x >> 4;
    const int h  = blockIdx.x & 15;
    const int qt = 15 - blockIdx.y;          // heavy blocks launch first (LPT)
    const uint32_t sb = smem_u32(sm2);

    // ---- load Q tile (128 rows x 128 d), hi/lo ----
    const size_t qoff = (((size_t)(b*S_ + qt*128))*H_ + h) * DH_;
    #pragma unroll
    for (int i = 0; i < 8; ++i) {
        int u = tid + i * 256;               // 2048 uint4 per array
        int r = u >> 4, c = u & 15;
        size_t go = qoff + (size_t)r * (H_*DH_) + c * 8;
        uint32_t so = (r * FA_STR + c * 8) * 2;
        *(uint4*)(sm2 + QH_OFF + so) = *(const uint4*)(g_qh + go);
        *(uint4*)(sm2 + QL_OFF + so) = *(const uint4*)(g_ql + go);
    }

    float o[16][4];
    #pragma unroll
    for (int nt = 0; nt < 16; ++nt) { o[nt][0]=o[nt][1]=o[nt][2]=o[nt][3]=0.f; }
    float m0 = -1e30f, m1 = -1e30f, l0 = 0.f, l1 = 0.f;

    // ldmatrix base addresses
    const uint32_t aBase = sb + ((w*16 + (lane&7) + ((lane>>3)&1)*8) * FA_STR + (lane>>4)*8) * 2;
    const uint32_t kBase = sb + KH_OFF + (((lane&7) + ((lane>>4)&1)*8) * FA_STR + ((lane>>3)&1)*8) * 2;
    const uint32_t vBase = sb + VH_OFF + (((lane&7) + ((lane>>3)&1)*8) * FA_STR + ((lane>>4)&1)*8) * 2;

    const int nkt = 2*qt + 2;
    for (int kt = 0; kt < nkt; ++kt) {
        // ---- load K/V tiles (64 rows x 128), 4 arrays ----
        {
            const size_t kro = (size_t)(b*S_ + kt*64) * DH_;
            #pragma unroll
            for (int i = 0; i < 4; ++i) {
                int u = tid + i * 256;       // 1024 uint4 per array
                int r = u >> 4, c = u & 15;
                size_t go = kro + (size_t)r * DH_ + c * 8;
                uint32_t so = (r * FA_STR + c * 8) * 2;
                *(uint4*)(sm2 + KH_OFF + so) = *(const uint4*)(g_kh + go);
                *(uint4*)(sm2 + KL_OFF + so) = *(const uint4*)(g_kl + go);
                *(uint4*)(sm2 + VH_OFF + so) = *(const uint4*)(g_vh + go);
                *(uint4*)(sm2 + VL_OFF + so) = *(const uint4*)(g_vl + go);
            }
        }
        __syncthreads();

        // ---- QK^T: scores s[8 ntiles][4] ----
        float s[8][4];
        #pragma unroll
        for (int nt = 0; nt < 8; ++nt) { s[nt][0]=s[nt][1]=s[nt][2]=s[nt][3]=0.f; }

        #pragma unroll
        for (int ks = 0; ks < 8; ++ks) {
            uint32_t ah[4], al[4];
            LDSM_X4(ah[0], ah[1], ah[2], ah[3], aBase + ks*32);
            LDSM_X4(al[0], al[1], al[2], al[3], aBase + QL_OFF + ks*32);
            #pragma unroll
            for (int np = 0; np < 4; ++np) {
                uint32_t bh4[4], bl4[4];
                uint32_t kOff = (uint32_t)(np*16*FA_STR*2 + ks*32);
                LDSM_X4(bh4[0], bh4[1], bh4[2], bh4[3], kBase + kOff);
                LDSM_X4(bl4[0], bl4[1], bl4[2], bl4[3], kBase + (KL_OFF - KH_OFF) + kOff);
                MMA16816(s[2*np],   ah[0],ah[1],ah[2],ah[3], bh4[0], bh4[1]);
                MMA16816(s[2*np+1], ah[0],ah[1],ah[2],ah[3], bh4[2], bh4[3]);
                MMA16816(s[2*np],   ah[0],ah[1],ah[2],ah[3], bl4[0], bl4[1]);
                MMA16816(s[2*np+1], ah[0],ah[1],ah[2],ah[3], bl4[2], bl4[3]);
                MMA16816(s[2*np],   al[0],al[1],al[2],al[3], bh4[0], bh4[1]);
                MMA16816(s[2*np+1], al[0],al[1],al[2],al[3], bh4[2], bh4[3]);
            }
        }

        // ---- causal mask (only last two ktiles of this q-block) ----
        if (kt >= 2*qt) {
            const int rg = qt*128 + w*16 + (lane >> 2);
            const int cb = kt*64 + (lane & 3)*2;
            #pragma unroll
            for (int nt = 0; nt < 8; ++nt) {
                int cg = cb + nt*8;
                if (cg     > rg)     s[nt][0] = -1e30f;
                if (cg + 1 > rg)     s[nt][1] = -1e30f;
                if (cg     > rg + 8) s[nt][2] = -1e30f;
                if (cg + 1 > rg + 8) s[nt][3] = -1e30f;
            }
        }

        // ---- online softmax (rows r=lane>>2 and r+8; quad reduce) ----
        float mx0 = -1e30f, mx1 = -1e30f;
        #pragma unroll
        for (int nt = 0; nt < 8; ++nt) {
            mx0 = fmaxf(mx0, fmaxf(s[nt][0], s[nt][1]));
            mx1 = fmaxf(mx1, fmaxf(s[nt][2], s[nt][3]));
        }
        mx0 = fmaxf(mx0, __shfl_xor_sync(0xffffffffu, mx0, 1));
        mx0 = fmaxf(mx0, __shfl_xor_sync(0xffffffffu, mx0, 2));
        mx1 = fmaxf(mx1, __shfl_xor_sync(0xffffffffu, mx1, 1));
        mx1 = fmaxf(mx1, __shfl_xor_sync(0xffffffffu, mx1, 2));
        float mn0 = fmaxf(m0, mx0), mn1 = fmaxf(m1, mx1);
        float cr0 = fexp(m0 - mn0), cr1 = fexp(m1 - mn1);
        float rs0 = 0.f, rs1 = 0.f;
        #pragma unroll
        for (int nt = 0; nt < 8; ++nt) {
            s[nt][0] = fexp(s[nt][0] - mn0);
            s[nt][1] = fexp(s[nt][1] - mn0);
            s[nt][2] = fexp(s[nt][2] - mn1);
            s[nt][3] = fexp(s[nt][3] - mn1);
            rs0 += s[nt][0] + s[nt][1];
            rs1 += s[nt][2] + s[nt][3];
        }
        rs0 += __shfl_xor_sync(0xffffffffu, rs0, 1);
        rs0 += __shfl_xor_sync(0xffffffffu, rs0, 2);
        rs1 += __shfl_xor_sync(0xffffffffu, rs1, 1);
        rs1 += __shfl_xor_sync(0xffffffffu, rs1, 2);
        l0 = l0*cr0 + rs0;  l1 = l1*cr1 + rs1;
        m0 = mn0;  m1 = mn1;
        #pragma unroll
        for (int nt = 0; nt < 16; ++nt) {
            o[nt][0] *= cr0; o[nt][1] *= cr0; o[nt][2] *= cr1; o[nt][3] *= cr1;
        }

        // ---- PV: repack P (C-frag -> A-frag identity), hi/lo, 3 terms ----
        #pragma unroll
        for (int ks = 0; ks < 4; ++ks) {
            uint32_t ph[4], pl[4];
            {
                float p00=s[2*ks][0], p01=s[2*ks][1], p02=s[2*ks][2], p03=s[2*ks][3];
                float p10=s[2*ks+1][0], p11=s[2*ks+1][1], p12=s[2*ks+1][2], p13=s[2*ks+1][3];
                __nv_bfloat16 h00=__float2bfloat16_rn(p00), h01=__float2bfloat16_rn(p01);
                __nv_bfloat16 h02=__float2bfloat16_rn(p02), h03=__float2bfloat16_rn(p03);
                __nv_bfloat16 h10=__float2bfloat16_rn(p10), h11=__float2bfloat16_rn(p11);
                __nv_bfloat16 h12=__float2bfloat16_rn(p12), h13=__float2bfloat16_rn(p13);
                ph[0] = pack2(h00, h01);  ph[1] = pack2(h02, h03);
                ph[2] = pack2(h10, h11);  ph[3] = pack2(h12, h13);
                pl[0] = pack2(__float2bfloat16_rn(p00-__bfloat162float(h00)),
                              __float2bfloat16_rn(p01-__bfloat162float(h01)));
                pl[1] = pack2(__float2bfloat16_rn(p02-__bfloat162float(h02)),
                              __float2bfloat16_rn(p03-__bfloat162float(h03)));
                pl[2] = pack2(__float2bfloat16_rn(p10-__bfloat162float(h10)),
                              __float2bfloat16_rn(p11-__bfloat162float(h11)));
                pl[3] = pack2(__float2bfloat16_rn(p12-__bfloat162float(h12)),
                              __float2bfloat16_rn(p13-__bfloat162float(h13)));
            }
            #pragma unroll
            for (int np = 0; np < 8; ++np) {
                uint32_t vh4[4], vl4[4];
                uint32_t vOff = (uint32_t)(ks*16*FA_STR*2 + np*32);
                LDSM_X4T(vh4[0], vh4[1], vh4[2], vh4[3], vBase + vOff);
                LDSM_X4T(vl4[0], vl4[1], vl4[2], vl4[3], vBase + (VL_OFF - VH_OFF) + vOff);
                MMA16816(o[2*np],   ph[0],ph[1],ph[2],ph[3], vh4[0], vh4[1]);
                MMA16816(o[2*np+1], ph[0],ph[1],ph[2],ph[3], vh4[2], vh4[3]);
                MMA16816(o[2*np],   ph[0],ph[1],ph[2],ph[3], vl4[0], vl4[1]);
                MMA16816(o[2*np+1], ph[0],ph[1],ph[2],ph[3], vl4[2], vl4[3]);
                MMA16816(o[2*np],   pl[0],pl[1],pl[2],pl[3], vh4[0], vh4[1]);
                MMA16816(o[2*np+1], pl[0],pl[1],pl[2],pl[3], vh4[2], vh4[3]);
            }
        }
        __syncthreads();
    }

    // ---- epilogue ----
    float i0 = 1.0f / l0, i1 = 1.0f / l1;
    const int r0 = qt*128 + w*16 + (lane >> 2);
    float* ob0 = g_attn + (((size_t)(b*S_ + r0))*H_ + h) * DH_;
    float* ob1 = g_attn + (((size_t)(b*S_ + r0 + 8))*H_ + h) * DH_;
    #pragma unroll
    for (int nt = 0; nt < 16; ++nt) {
        int col = nt*8 + (lane & 3)*2;
        *(float2*)(ob0 + col) = make_float2(o[nt][0]*i0, o[nt][1]*i0);
        *(float2*)(ob1 + col) = make_float2(o[nt][2]*i1, o[nt][3]*i1);
    }
}

// ---------------- launch ----------------
extern "C" void kernel_launch(void* const* d_in, const int* in_sizes, int n_in,
                              void* d_out, int out_size) {
    const float* x        = (const float*)d_in[0];
    const float* q_weight = (const float*)d_in[1];
    const float* q_bias   = (const float*)d_in[2];
    const float* kv_weight= (const float*)d_in[3];
    const float* kv_bias  = (const float*)d_in[4];
    const float* o_weight = (const float*)d_in[5];
    const float* o_bias   = (const float*)d_in[6];
    float* out = (float*)d_out;

    float *pq, *pkv, *pattn;
    cudaGetSymbolAddress((void**)&pq,    g_q);
    cudaGetSymbolAddress((void**)&pkv,   g_kv);
    cudaGetSymbolAddress((void**)&pattn, g_attn);

    cudaFuncSetAttribute(gemm_mma_kernel,
                         cudaFuncAttributeMaxDynamicSharedMemorySize, GEMM_DYN);
    cudaFuncSetAttribute(flash_attn_mma_kernel,
                         cudaFuncAttributeMaxDynamicSharedMemorySize, FA_BYTES);

    // 1. RoPE tables
    rope_table_kernel<<<(S_*64 + 255)/256, 256>>>();
    // 2. Q projection (mma.sync bf16 x3)
    gemm_mma_kernel<<<dim3(D_/128, M_/128), 256, GEMM_DYN>>>(
        x, q_weight, q_bias, pq, D_, D_);
    // 3. KV projection
    gemm_mma_kernel<<<dim3(256/128, M_/128), 256, GEMM_DYN>>>(
        x, kv_weight, kv_bias, pkv, D_, 256);
    // 4. RoPE on q -> bf16 hi/lo (scaled)
    rope_q_kernel<<<(M_*H_*64 + 255)/256, 256>>>();
    // 5. split kv -> k (RoPE) hi/lo, v hi/lo
    kv_split_kernel<<<(M_*64 + 255)/256, 256>>>();
    // 6. tensorized flash attention
    flash_attn_mma_kernel<<<dim3(B_*H_, S_/128), 256, FA_BYTES>>>();
    // 7. O projection -> d_out
    gemm_mma_kernel<<<dim3(D_/128, M_/128), 256, GEMM_DYN>>>(
        pattn, o_weight, o_bias, out, D_, D_);
}

// round 6
// speedup vs baseline: 3.0121x; 1.0909x over previous
#include <cuda_runtime.h>
#include <cuda_bf16.h>
#include <math.h>
#include <stdint.h>

#define B_  2
#define S_  2048
#define D_  2048
#define H_  16
#define DH_ 128
#define M_  (B_*S_)
#define SCALE_ 0.08838834764831845f  // 1/sqrt(128)

// ---------------- scratch (device globals; no allocations) ----------------
__device__ float g_cos[S_*64];
__device__ float g_sin[S_*64];
// presplit bf16 hi/lo operands
__device__ __nv_bfloat16 g_xh [(size_t)M_*D_],  g_xl [(size_t)M_*D_];
__device__ __nv_bfloat16 g_qwh[(size_t)D_*D_],  g_qwl[(size_t)D_*D_];
__device__ __nv_bfloat16 g_kvwh[(size_t)2*DH_*D_], g_kvwl[(size_t)2*DH_*D_];
__device__ __nv_bfloat16 g_owh[(size_t)D_*D_],  g_owl[(size_t)D_*D_];
__device__ __nv_bfloat16 g_qh [(size_t)M_*D_],  g_ql [(size_t)M_*D_];
__device__ __nv_bfloat16 g_kh [(size_t)M_*DH_], g_kl [(size_t)M_*DH_];
__device__ __nv_bfloat16 g_vh [(size_t)M_*DH_], g_vl [(size_t)M_*DH_];
__device__ __nv_bfloat16 g_ah [(size_t)M_*D_],  g_al [(size_t)M_*D_];

// =====================================================================
// helpers
// =====================================================================
__device__ __forceinline__ uint32_t smem_u32(const void* p) {
    uint32_t a;
    asm("{ .reg .u64 t; cvta.to.shared.u64 t, %1; cvt.u32.u64 %0, t; }"
        : "=r"(a) : "l"(p));
    return a;
}
__device__ __forceinline__ uint32_t pack2(__nv_bfloat16 a, __nv_bfloat16 b) {
    uint16_t x = *(uint16_t*)&a, y = *(uint16_t*)&b;
    return (uint32_t)x | ((uint32_t)y << 16);
}

#define LDSM_X4(r0, r1, r2, r3, addr) \
    asm volatile("ldmatrix.sync.aligned.m8n8.x4.shared.b16 {%0,%1,%2,%3}, [%4];" \
                 : "=r"(r0), "=r"(r1), "=r"(r2), "=r"(r3) : "r"(addr))
#define LDSM_X4T(r0, r1, r2, r3, addr) \
    asm volatile("ldmatrix.sync.aligned.m8n8.x4.trans.shared.b16 {%0,%1,%2,%3}, [%4];" \
                 : "=r"(r0), "=r"(r1), "=r"(r2), "=r"(r3) : "r"(addr))
#define MMA16816(d, a0, a1, a2, a3, b0, b1) \
    asm volatile("mma.sync.aligned.m16n8k16.row.col.f32.bf16.bf16.f32 " \
                 "{%0,%1,%2,%3}, {%4,%5,%6,%7}, {%8,%9}, {%0,%1,%2,%3};" \
                 : "+f"((d)[0]), "+f"((d)[1]), "+f"((d)[2]), "+f"((d)[3]) \
                 : "r"(a0), "r"(a1), "r"(a2), "r"(a3), "r"(b0), "r"(b1))

#define CP_A16(sm, gp) \
    asm volatile("cp.async.cg.shared.global [%0], [%1], 16;" :: "r"(sm), "l"(gp))
#define CP_COMMIT() asm volatile("cp.async.commit_group;" ::: "memory")
#define CP_WAIT(n)  asm volatile("cp.async.wait_group %0;" :: "n"(n) : "memory")

// fast exp on fma/alu pipes (no MUFU). x <= 0 expected; rel err ~3e-6.
__device__ __forceinline__ float fexp(float x) {
    x = fmaxf(x, -87.0f);
    float y = x * 1.44269504f;
    float i = rintf(y);
    float f = (y - i) * 0.69314718f;
    float p = 1.0f + f*(1.0f + f*(0.5f + f*(0.166666667f + f*(0.0416666667f + f*0.00833333f))));
    int e = (int)i;
    float sc = __int_as_float((e + 127) << 23);
    return p * sc;
}

// ---------------- split fp32 -> bf16 hi/lo ----------------
__global__ void split_kernel(const float* __restrict__ src,
                             __nv_bfloat16* __restrict__ hi,
                             __nv_bfloat16* __restrict__ lo, int n4) {
    int i = blockIdx.x * blockDim.x + threadIdx.x;
    if (i >= n4) return;
    float4 v = ((const float4*)src)[i];
    __nv_bfloat16 h0 = __float2bfloat16_rn(v.x);
    __nv_bfloat16 h1 = __float2bfloat16_rn(v.y);
    __nv_bfloat16 h2 = __float2bfloat16_rn(v.z);
    __nv_bfloat16 h3 = __float2bfloat16_rn(v.w);
    uint2 hv = make_uint2(pack2(h0, h1), pack2(h2, h3));
    uint2 lv = make_uint2(
        pack2(__float2bfloat16_rn(v.x - __bfloat162float(h0)),
              __float2bfloat16_rn(v.y - __bfloat162float(h1))),
        pack2(__float2bfloat16_rn(v.z - __bfloat162float(h2)),
              __float2bfloat16_rn(v.w - __bfloat162float(h3))));
    *(uint2*)(hi + (size_t)i * 4) = hv;
    *(uint2*)(lo + (size_t)i * 4) = lv;
}

// ---------------- RoPE table ----------------
__global__ void rope_table_kernel() {
    int idx = blockIdx.x * blockDim.x + threadIdx.x;
    if (idx >= S_*64) return;
    int s = idx >> 6;
    int i = idx & 63;
    float expo = (float)(2*i) / 128.0f;
    float inv  = 1.0f / powf(10000.0f, expo);
    float ang  = (float)s * inv;
    g_cos[idx] = cosf(ang);
    g_sin[idx] = sinf(ang);
}

// =====================================================================
// GEMM: C[M,N] = A[M,K] @ W[N,K]^T (+bias), presplit bf16 inputs,
// 3-term emulation, cp.async double-buffered, fused epilogues.
// mode 0: fp32 + bias -> Cf
// mode 1: bias + RoPE + scale + split -> oH/oL (Q; CTA N-block = one head)
// mode 2: blockIdx.x==0: bias+RoPE+split -> oH/oL (K); ==1: bias+split -> oH2/oL2 (V)
// =====================================================================
#define ASTRIDE 40
#define ARR_B   (128 * ASTRIDE * 2)      // 10240 B / array
#define STAGE_B (4 * ARR_B)              // 40960 B / stage
#define CS_STR  132
#define GEMM_DYN 81920                   // 2 stages; >= 128*132*4 epilogue

__global__ __launch_bounds__(256, 2)
void gemm_mma_kernel(const __nv_bfloat16* __restrict__ Ah_g,
                     const __nv_bfloat16* __restrict__ Al_g,
                     const __nv_bfloat16* __restrict__ Bh_g,
                     const __nv_bfloat16* __restrict__ Bl_g,
                     const float* __restrict__ bias,
                     float* __restrict__ Cf,
                     __nv_bfloat16* __restrict__ oH,  __nv_bfloat16* __restrict__ oL,
                     __nv_bfloat16* __restrict__ oH2, __nv_bfloat16* __restrict__ oL2,
                     int K, int N, int mode) {
    extern __shared__ char dsm[];
    const int tid  = threadIdx.x;
    const int lane = tid & 31, wid = tid >> 5;
    const int wm = wid & 3;
    const int wn = wid >> 2;
    const uint32_t sbase = smem_u32(dsm);

    const __nv_bfloat16* a0 = Ah_g + (size_t)blockIdx.y * 128 * K;
    const __nv_bfloat16* a1 = Al_g + (size_t)blockIdx.y * 128 * K;
    const __nv_bfloat16* b0 = Bh_g + (size_t)blockIdx.x * 128 * K;
    const __nv_bfloat16* b1 = Bl_g + (size_t)blockIdx.x * 128 * K;

    float acc[2][8][4];
    #pragma unroll
    for (int mt = 0; mt < 2; ++mt)
        #pragma unroll
        for (int nt = 0; nt < 8; ++nt)
            #pragma unroll
            for (int j = 0; j < 4; ++j) acc[mt][nt][j] = 0.f;

    const int aRow = wm * 32 + (lane & 7) + ((lane >> 3) & 1) * 8;
    const int aCol = (lane >> 4) * 8;
    const int bRow = wn * 64 + (lane & 7) + ((lane >> 4) & 1) * 8;
    const int bCol = ((lane >> 3) & 1) * 8;
    const int kc = K >> 5;

    // 8 cp.asyncs per thread per chunk: arrays [Ah,Al,Bh,Bl] x 512 copies
    auto issue = [&](int c) {
        const int koff = c * 32;
        const uint32_t sst = sbase + (uint32_t)(c & 1) * STAGE_B;
        #pragma unroll
        for (int i = 0; i < 8; ++i) {
            const int arr = i >> 1;                  // compile-time
            int rem = (i & 1) * 256 + tid;           // 0..511
            int r = rem >> 2, c4 = rem & 3;
            const __nv_bfloat16* gp =
                (arr == 0 ? a0 : arr == 1 ? a1 : arr == 2 ? b0 : b1)
                + (size_t)r * K + koff + c4 * 8;
            uint32_t sm = sst + arr * ARR_B + r * 80 + c4 * 16;
            CP_A16(sm, gp);
        }
        CP_COMMIT();
    };

    issue(0);
    if (kc > 1) issue(1);

    for (int c = 0; c < kc; ++c) {
        if (c + 1 < kc) { CP_WAIT(1); } else { CP_WAIT(0); }
        __syncthreads();

        const uint32_t sa = sbase + (uint32_t)(c & 1) * STAGE_B;
        const uint32_t aBase = sa + (aRow * ASTRIDE + aCol) * 2;
        const uint32_t bBase = sa + 2 * ARR_B + (bRow * ASTRIDE + bCol) * 2;

        #pragma unroll
        for (int kp = 0; kp < 2; ++kp) {
            uint32_t ah[2][4], al[2][4];
            #pragma unroll
            for (int mt = 0; mt < 2; ++mt) {
                uint32_t ad = aBase + (mt * 16 * ASTRIDE + kp * 16) * 2;
                LDSM_X4(ah[mt][0], ah[mt][1], ah[mt][2], ah[mt][3], ad);
                LDSM_X4(al[mt][0], al[mt][1], al[mt][2], al[mt][3], ad + ARR_B);
            }
            #pragma unroll
            for (int np = 0; np < 4; ++np) {
                uint32_t bh[4], bl[4];
                uint32_t bd = bBase + (np * 16 * ASTRIDE + kp * 16) * 2;
                LDSM_X4(bh[0], bh[1], bh[2], bh[3], bd);
                LDSM_X4(bl[0], bl[1], bl[2], bl[3], bd + ARR_B);
                const int nt = np * 2;
                MMA16816(acc[0][nt],   ah[0][0], ah[0][1], ah[0][2], ah[0][3], bh[0], bh[1]);
                MMA16816(acc[0][nt+1], ah[0][0], ah[0][1], ah[0][2], ah[0][3], bh[2], bh[3]);
                MMA16816(acc[1][nt],   ah[1][0], ah[1][1], ah[1][2], ah[1][3], bh[0], bh[1]);
                MMA16816(acc[1][nt+1], ah[1][0], ah[1][1], ah[1][2], ah[1][3], bh[2], bh[3]);
                MMA16816(acc[0][nt],   ah[0][0], ah[0][1], ah[0][2], ah[0][3], bl[0], bl[1]);
                MMA16816(acc[0][nt+1], ah[0][0], ah[0][1], ah[0][2], ah[0][3], bl[2], bl[3]);
                MMA16816(acc[1][nt],   ah[1][0], ah[1][1], ah[1][2], ah[1][3], bl[0], bl[1]);
                MMA16816(acc[1][nt+1], ah[1][0], ah[1][1], ah[1][2], ah[1][3], bl[2], bl[3]);
                MMA16816(acc[0][nt],   al[0][0], al[0][1], al[0][2], al[0][3], bh[0], bh[1]);
                MMA16816(acc[0][nt+1], al[0][0], al[0][1], al[0][2], al[0][3], bh[2], bh[3]);
                MMA16816(acc[1][nt],   al[1][0], al[1][1], al[1][2], al[1][3], bh[0], bh[1]);
                MMA16816(acc[1][nt+1], al[1][0], al[1][1], al[1][2], al[1][3], bh[2], bh[3]);
            }
        }
        __syncthreads();
        if (c + 2 < kc) issue(c + 2);
    }

    if (mode == 0) {
        const int r0 = blockIdx.y * 128 + wm * 32 + (lane >> 2);
        const int c0 = blockIdx.x * 128 + wn * 64 + (lane & 3) * 2;
        #pragma unroll
        for (int mt = 0; mt < 2; ++mt)
            #pragma unroll
            for (int nt = 0; nt < 8; ++nt) {
                int row = r0 + mt * 16;
                int col = c0 + nt * 8;
                float bb0 = __ldg(bias + col), bb1 = __ldg(bias + col + 1);
                *(float2*)(Cf + (size_t)row * N + col) =
                    make_float2(acc[mt][nt][0] + bb0, acc[mt][nt][1] + bb1);
                *(float2*)(Cf + (size_t)(row + 8) * N + col) =
                    make_float2(acc[mt][nt][2] + bb0, acc[mt][nt][3] + bb1);
            }
        return;
    }

    // ---- modes 1/2: stage tile (+bias) to smem fp32 ----
    float* Cs = (float*)dsm;
    const int rl = wm * 32 + (lane >> 2);
    const int cl = wn * 64 + (lane & 3) * 2;
    #pragma unroll
    for (int mt = 0; mt < 2; ++mt)
        #pragma unroll
        for (int nt = 0; nt < 8; ++nt) {
            int rr = rl + mt * 16;
            int cc = cl + nt * 8;
            float bb0 = __ldg(bias + blockIdx.x * 128 + cc);
            float bb1 = __ldg(bias + blockIdx.x * 128 + cc + 1);
            Cs[rr * CS_STR + cc]       = acc[mt][nt][0] + bb0;
            Cs[rr * CS_STR + cc + 1]   = acc[mt][nt][1] + bb1;
            Cs[(rr+8) * CS_STR + cc]   = acc[mt][nt][2] + bb0;
            Cs[(rr+8) * CS_STR + cc+1] = acc[mt][nt][3] + bb1;
        }
    __syncthreads();

    const bool doRope = (mode == 1) || (mode == 2 && blockIdx.x == 0);
    if (doRope) {
        const float sc   = (mode == 1) ? SCALE_ : 1.0f;
        const int   Nout = (mode == 1) ? D_ : DH_;
        const int   cb   = (mode == 1) ? (int)blockIdx.x * 128 : 0;
        #pragma unroll 4
        for (int t = 0; t < 32; ++t) {
            int idx = t * 256 + tid;             // 8192 pairs
            int r = idx >> 6, d = idx & 63;
            int rowg = blockIdx.y * 128 + r;
            int s = rowg & (S_ - 1);
            float c1 = Cs[r * CS_STR + d];
            float c2 = Cs[r * CS_STR + d + 64];
            float cv = g_cos[s * 64 + d], sv = g_sin[s * 64 + d];
            float y1 = (c1 * cv - c2 * sv) * sc;
            float y2 = (c2 * cv + c1 * sv) * sc;
            size_t off = (size_t)rowg * Nout + cb + d;
            __nv_bfloat16 h1 = __float2bfloat16_rn(y1);
            __nv_bfloat16 h2 = __float2bfloat16_rn(y2);
            oH[off]      = h1;
            oH[off + 64] = h2;
            oL[off]      = __float2bfloat16_rn(y1 - __bfloat162float(h1));
            oL[off + 64] = __float2bfloat16_rn(y2 - __bfloat162float(h2));
        }
    } else {
        // V: plain split
        #pragma unroll 4
        for (int t = 0; t < 64; ++t) {
            int idx = t * 256 + tid;             // 16384 elems
            int r = idx >> 7, d = idx & 127;
            int rowg = blockIdx.y * 128 + r;
            float v = Cs[r * CS_STR + d];
            size_t off = (size_t)rowg * DH_ + d;
            __nv_bfloat16 hv = __float2bfloat16_rn(v);
            oH2[off] = hv;
            oL2[off] = __float2bfloat16_rn(v - __bfloat162float(hv));
        }
    }
}

// =====================================================================
// tensorized flash attention (causal MQA), cp.async double-buffered K/V
// =====================================================================
#define FA_STR   136
#define FQ_ARR   (128 * FA_STR * 2)      // 34816
#define FKV_ARR  (64 * FA_STR * 2)       // 17408
#define FKV_SET  (4 * FKV_ARR)           // 69632
#define FKV_OFF  (2 * FQ_ARR)            // 69632
#define FA_BYTES (FKV_OFF + 2 * FKV_SET) // 208896

__global__ __launch_bounds__(256, 1)
void flash_attn_mma_kernel() {
    extern __shared__ char sm2[];
    const int tid  = threadIdx.x;
    const int lane = tid & 31, w = tid >> 5;
    const int b  = blockIdx.x >> 4;
    const int h  = blockIdx.x & 15;
    const int qt = 15 - blockIdx.y;          // LPT
    const uint32_t sb = smem_u32(sm2);

    // ---- load Q tile (128 x 128 bf16 hi/lo) ----
    const size_t qoff = (size_t)(b*S_ + qt*128) * D_ + (size_t)h * DH_;
    #pragma unroll
    for (int i = 0; i < 8; ++i) {
        int u = tid + i * 256;
        int r = u >> 4, c = u & 15;
        size_t go = qoff + (size_t)r * D_ + c * 8;
        uint32_t so = (r * FA_STR + c * 8) * 2;
        *(uint4*)(sm2 + so)          = *(const uint4*)(g_qh + go);
        *(uint4*)(sm2 + FQ_ARR + so) = *(const uint4*)(g_ql + go);
    }

    float o[16][4];
    #pragma unroll
    for (int nt = 0; nt < 16; ++nt) { o[nt][0]=o[nt][1]=o[nt][2]=o[nt][3]=0.f; }
    float m0 = -1e30f, m1 = -1e30f, l0 = 0.f, l1 = 0.f;

    const uint32_t aBase = sb + ((w*16 + (lane&7) + ((lane>>3)&1)*8) * FA_STR + (lane>>4)*8) * 2;
    const uint32_t kLane = (((lane&7) + ((lane>>4)&1)*8) * FA_STR + ((lane>>3)&1)*8) * 2;
    const uint32_t vLane = (((lane&7) + ((lane>>3)&1)*8) * FA_STR + ((lane>>4)&1)*8) * 2;

    const int nkt = 2*qt + 2;

    auto issue_kv = [&](int kt) {
        const size_t kro = (size_t)(b*S_ + kt*64) * DH_;
        const uint32_t sOff = sb + FKV_OFF + (uint32_t)(kt & 1) * FKV_SET;
        #pragma unroll
        for (int i = 0; i < 16; ++i) {
            const int arr = i >> 2;              // compile-time
            int rem = (i & 3) * 256 + tid;       // 0..1023
            int r = rem >> 4, c = rem & 15;
            const __nv_bfloat16* gp =
                (arr == 0 ? g_kh : arr == 1 ? g_kl : arr == 2 ? g_vh : g_vl)
                + kro + (size_t)r * DH_ + c * 8;
            uint32_t sm = sOff + arr * FKV_ARR + r * (FA_STR*2) + c * 16;
            CP_A16(sm, gp);
        }
        CP_COMMIT();
    };

    issue_kv(0);
    if (nkt > 1) issue_kv(1);

    for (int kt = 0; kt < nkt; ++kt) {
        if (kt + 1 < nkt) { CP_WAIT(1); } else { CP_WAIT(0); }
        __syncthreads();

        const uint32_t setOff = FKV_OFF + (uint32_t)(kt & 1) * FKV_SET;
        const uint32_t kBase = sb + setOff + kLane;
        const uint32_t vBase = sb + setOff + 2 * FKV_ARR + vLane;

        // ---- QK^T ----
        float s[8][4];
        #pragma unroll
        for (int nt = 0; nt < 8; ++nt) { s[nt][0]=s[nt][1]=s[nt][2]=s[nt][3]=0.f; }

        #pragma unroll
        for (int ks = 0; ks < 8; ++ks) {
            uint32_t ah[4], al[4];
            LDSM_X4(ah[0], ah[1], ah[2], ah[3], aBase + ks*32);
            LDSM_X4(al[0], al[1], al[2], al[3], aBase + FQ_ARR + ks*32);
            #pragma unroll
            for (int np = 0; np < 4; ++np) {
                uint32_t bh4[4], bl4[4];
                uint32_t kOff = (uint32_t)(np*16*FA_STR*2 + ks*32);
                LDSM_X4(bh4[0], bh4[1], bh4[2], bh4[3], kBase + kOff);
                LDSM_X4(bl4[0], bl4[1], bl4[2], bl4[3], kBase + FKV_ARR + kOff);
                MMA16816(s[2*np],   ah[0],ah[1],ah[2],ah[3], bh4[0], bh4[1]);
                MMA16816(s[2*np+1], ah[0],ah[1],ah[2],ah[3], bh4[2], bh4[3]);
                MMA16816(s[2*np],   ah[0],ah[1],ah[2],ah[3], bl4[0], bl4[1]);
                MMA16816(s[2*np+1], ah[0],ah[1],ah[2],ah[3], bl4[2], bl4[3]);
                MMA16816(s[2*np],   al[0],al[1],al[2],al[3], bh4[0], bh4[1]);
                MMA16816(s[2*np+1], al[0],al[1],al[2],al[3], bh4[2], bh4[3]);
            }
        }

        // ---- causal mask ----
        if (kt >= 2*qt) {
            const int rg = qt*128 + w*16 + (lane >> 2);
            const int cb = kt*64 + (lane & 3)*2;
            #pragma unroll
            for (int nt = 0; nt < 8; ++nt) {
                int cg = cb + nt*8;
                if (cg     > rg)     s[nt][0] = -1e30f;
                if (cg + 1 > rg)     s[nt][1] = -1e30f;
                if (cg     > rg + 8) s[nt][2] = -1e30f;
                if (cg + 1 > rg + 8) s[nt][3] = -1e30f;
            }
        }

        // ---- online softmax ----
        float mx0 = -1e30f, mx1 = -1e30f;
        #pragma unroll
        for (int nt = 0; nt < 8; ++nt) {
            mx0 = fmaxf(mx0, fmaxf(s[nt][0], s[nt][1]));
            mx1 = fmaxf(mx1, fmaxf(s[nt][2], s[nt][3]));
        }
        mx0 = fmaxf(mx0, __shfl_xor_sync(0xffffffffu, mx0, 1));
        mx0 = fmaxf(mx0, __shfl_xor_sync(0xffffffffu, mx0, 2));
        mx1 = fmaxf(mx1, __shfl_xor_sync(0xffffffffu, mx1, 1));
        mx1 = fmaxf(mx1, __shfl_xor_sync(0xffffffffu, mx1, 2));
        float mn0 = fmaxf(m0, mx0), mn1 = fmaxf(m1, mx1);
        float cr0 = fexp(m0 - mn0), cr1 = fexp(m1 - mn1);
        float rs0 = 0.f, rs1 = 0.f;
        #pragma unroll
        for (int nt = 0; nt < 8; ++nt) {
            s[nt][0] = fexp(s[nt][0] - mn0);
            s[nt][1] = fexp(s[nt][1] - mn0);
            s[nt][2] = fexp(s[nt][2] - mn1);
            s[nt][3] = fexp(s[nt][3] - mn1);
            rs0 += s[nt][0] + s[nt][1];
            rs1 += s[nt][2] + s[nt][3];
        }
        rs0 += __shfl_xor_sync(0xffffffffu, rs0, 1);
        rs0 += __shfl_xor_sync(0xffffffffu, rs0, 2);
        rs1 += __shfl_xor_sync(0xffffffffu, rs1, 1);
        rs1 += __shfl_xor_sync(0xffffffffu, rs1, 2);
        l0 = l0*cr0 + rs0;  l1 = l1*cr1 + rs1;
        m0 = mn0;  m1 = mn1;
        #pragma unroll
        for (int nt = 0; nt < 16; ++nt) {
            o[nt][0] *= cr0; o[nt][1] *= cr0; o[nt][2] *= cr1; o[nt][3] *= cr1;
        }

        // ---- PV ----
        #pragma unroll
        for (int ks = 0; ks < 4; ++ks) {
            uint32_t ph[4], pl[4];
            {
                float p00=s[2*ks][0], p01=s[2*ks][1], p02=s[2*ks][2], p03=s[2*ks][3];
                float p10=s[2*ks+1][0], p11=s[2*ks+1][1], p12=s[2*ks+1][2], p13=s[2*ks+1][3];
                __nv_bfloat16 h00=__float2bfloat16_rn(p00), h01=__float2bfloat16_rn(p01);
                __nv_bfloat16 h02=__float2bfloat16_rn(p02), h03=__float2bfloat16_rn(p03);
                __nv_bfloat16 h10=__float2bfloat16_rn(p10), h11=__float2bfloat16_rn(p11);
                __nv_bfloat16 h12=__float2bfloat16_rn(p12), h13=__float2bfloat16_rn(p13);
                ph[0] = pack2(h00, h01);  ph[1] = pack2(h02, h03);
                ph[2] = pack2(h10, h11);  ph[3] = pack2(h12, h13);
                pl[0] = pack2(__float2bfloat16_rn(p00-__bfloat162float(h00)),
                              __float2bfloat16_rn(p01-__bfloat162float(h01)));
                pl[1] = pack2(__float2bfloat16_rn(p02-__bfloat162float(h02)),
                              __float2bfloat16_rn(p03-__bfloat162float(h03)));
                pl[2] = pack2(__float2bfloat16_rn(p10-__bfloat162float(h10)),
                              __float2bfloat16_rn(p11-__bfloat162float(h11)));
                pl[3] = pack2(__float2bfloat16_rn(p12-__bfloat162float(h12)),
                              __float2bfloat16_rn(p13-__bfloat162float(h13)));
            }
            #pragma unroll
            for (int np = 0; np < 8; ++np) {
                uint32_t vh4[4], vl4[4];
                uint32_t vOff = (uint32_t)(ks*16*FA_STR*2 + np*32);
                LDSM_X4T(vh4[0], vh4[1], vh4[2], vh4[3], vBase + vOff);
                LDSM_X4T(vl4[0], vl4[1], vl4[2], vl4[3], vBase + FKV_ARR + vOff);
                MMA16816(o[2*np],   ph[0],ph[1],ph[2],ph[3], vh4[0], vh4[1]);
                MMA16816(o[2*np+1], ph[0],ph[1],ph[2],ph[3], vh4[2], vh4[3]);
                MMA16816(o[2*np],   ph[0],ph[1],ph[2],ph[3], vl4[0], vl4[1]);
                MMA16816(o[2*np+1], ph[0],ph[1],ph[2],ph[3], vl4[2], vl4[3]);
                MMA16816(o[2*np],   pl[0],pl[1],pl[2],pl[3], vh4[0], vh4[1]);
                MMA16816(o[2*np+1], pl[0],pl[1],pl[2],pl[3], vh4[2], vh4[3]);
            }
        }
        __syncthreads();
        if (kt + 2 < nkt) issue_kv(kt + 2);
    }

    // ---- epilogue: write bf16 hi/lo for O projection ----
    float i0 = 1.0f / l0, i1 = 1.0f / l1;
    const int r0 = qt*128 + w*16 + (lane >> 2);
    const size_t ob0 = (size_t)(b*S_ + r0)     * D_ + (size_t)h * DH_;
    const size_t ob1 = (size_t)(b*S_ + r0 + 8) * D_ + (size_t)h * DH_;
    #pragma unroll
    for (int nt = 0; nt < 16; ++nt) {
        int col = nt*8 + (lane & 3)*2;
        float v0 = o[nt][0]*i0, v1 = o[nt][1]*i0;
        float v2 = o[nt][2]*i1, v3 = o[nt][3]*i1;
        __nv_bfloat16 h0 = __float2bfloat16_rn(v0), h1 = __float2bfloat16_rn(v1);
        __nv_bfloat16 h2 = __float2bfloat16_rn(v2), h3 = __float2bfloat16_rn(v3);
        *(uint32_t*)(g_ah + ob0 + col) = pack2(h0, h1);
        *(uint32_t*)(g_al + ob0 + col) =
            pack2(__float2bfloat16_rn(v0 - __bfloat162float(h0)),
                  __float2bfloat16_rn(v1 - __bfloat162float(h1)));
        *(uint32_t*)(g_ah + ob1 + col) = pack2(h2, h3);
        *(uint32_t*)(g_al + ob1 + col) =
            pack2(__float2bfloat16_rn(v2 - __bfloat162float(h2)),
                  __float2bfloat16_rn(v3 - __bfloat162float(h3)));
    }
}

// ---------------- launch ----------------
extern "C" void kernel_launch(void* const* d_in, const int* in_sizes, int n_in,
                              void* d_out, int out_size) {
    const float* x        = (const float*)d_in[0];
    const float* q_weight = (const float*)d_in[1];
    const float* q_bias   = (const float*)d_in[2];
    const float* kv_weight= (const float*)d_in[3];
    const float* kv_bias  = (const float*)d_in[4];
    const float* o_weight = (const float*)d_in[5];
    const float* o_bias   = (const float*)d_in[6];
    float* out = (float*)d_out;

    __nv_bfloat16 *xh, *xl, *qwh, *qwl, *kvwh, *kvwl, *owh, *owl;
    __nv_bfloat16 *qh, *ql, *kh, *kl, *vh, *vl, *ah, *al;
    cudaGetSymbolAddress((void**)&xh,   g_xh);   cudaGetSymbolAddress((void**)&xl,   g_xl);
    cudaGetSymbolAddress((void**)&qwh,  g_qwh);  cudaGetSymbolAddress((void**)&qwl,  g_qwl);
    cudaGetSymbolAddress((void**)&kvwh, g_kvwh); cudaGetSymbolAddress((void**)&kvwl, g_kvwl);
    cudaGetSymbolAddress((void**)&owh,  g_owh);  cudaGetSymbolAddress((void**)&owl,  g_owl);
    cudaGetSymbolAddress((void**)&qh,   g_qh);   cudaGetSymbolAddress((void**)&ql,   g_ql);
    cudaGetSymbolAddress((void**)&kh,   g_kh);   cudaGetSymbolAddress((void**)&kl,   g_kl);
    cudaGetSymbolAddress((void**)&vh,   g_vh);   cudaGetSymbolAddress((void**)&vl,   g_vl);
    cudaGetSymbolAddress((void**)&ah,   g_ah);   cudaGetSymbolAddress((void**)&al,   g_al);

    cudaFuncSetAttribute(gemm_mma_kernel,
                         cudaFuncAttributeMaxDynamicSharedMemorySize, GEMM_DYN);
    cudaFuncSetAttribute(flash_attn_mma_kernel,
                         cudaFuncAttributeMaxDynamicSharedMemorySize, FA_BYTES);

    // 1. RoPE tables + presplits
    rope_table_kernel<<<(S_*64 + 255)/256, 256>>>();
    split_kernel<<<(M_*D_/4 + 255)/256, 256>>>(x, xh, xl, M_*D_/4);
    split_kernel<<<(D_*D_/4 + 255)/256, 256>>>(q_weight, qwh, qwl, D_*D_/4);
    split_kernel<<<(2*DH_*D_/4 + 255)/256, 256>>>(kv_weight, kvwh, kvwl, 2*DH_*D_/4);
    split_kernel<<<(D_*D_/4 + 255)/256, 256>>>(o_weight, owh, owl, D_*D_/4);

    // 2. Q projection (mode 1: bias + RoPE + scale + split)
    gemm_mma_kernel<<<dim3(D_/128, M_/128), 256, GEMM_DYN>>>(
        xh, xl, qwh, qwl, q_bias, nullptr, qh, ql, nullptr, nullptr, D_, D_, 1);
    // 3. KV projection (mode 2: K rope / V split)
    gemm_mma_kernel<<<dim3(2, M_/128), 256, GEMM_DYN>>>(
        xh, xl, kvwh, kvwl, kv_bias, nullptr, kh, kl, vh, vl, D_, 256, 2);
    // 4. attention
    flash_attn_mma_kernel<<<dim3(B_*H_, S_/128), 256, FA_BYTES>>>();
    // 5. O projection (mode 0) -> d_out
    gemm_mma_kernel<<<dim3(D_/128, M_/128), 256, GEMM_DYN>>>(
        ah, al, owh, owl, o_bias, out, nullptr, nullptr, nullptr, nullptr, D_, D_, 0);
}